// round 1
// baseline (speedup 1.0000x reference)
#include <cuda_runtime.h>
#include <math_constants.h>

#define BATCH 32
#define CDIM  1024
#define CI    512
#define NPOS  784

// -------- scratch (static __device__ arrays; no allocation allowed) --------
__device__ float g_TP[(size_t)BATCH * CDIM * NPOS];   // theta rows 0..511, phi rows 512..1023 (102.8 MB)
__device__ float g_F[(size_t)BATCH * NPOS * NPOS];    // f, then overwritten with exp(f - rowmax)  (78.7 MB)
__device__ float g_rscale[BATCH * NPOS];              // 1/(rowsum * N)
__device__ float g_abar[BATCH * NPOS];                // column means of attn
__device__ float g_xw[BATCH * CDIM];                  // X @ a_bar
__device__ float g_xbar[BATCH * CDIM];                // mean_n X
__device__ float g_ybar[BATCH * CI];
__device__ float g_pooled[BATCH * CDIM];
__device__ float g_h[BATCH * CI];

// ===========================================================================
// GEMM1: TP[b][m][n] = sum_k W(m,k) * X[b][k][n] + bias(m)
//   W rows 0..511 = Wth, 512..1023 = Wph   (both [512,1024] row-major)
//   tile 128(M) x 112(N) x 16(K), 256 threads, 8x7 per thread
// ===========================================================================
__global__ __launch_bounds__(256) void gemm1_kernel(
    const float* __restrict__ x,
    const float* __restrict__ Wth, const float* __restrict__ bth,
    const float* __restrict__ Wph, const float* __restrict__ bph)
{
    const int b  = blockIdx.z;
    const int m0 = blockIdx.y * 128;
    const int n0 = blockIdx.x * 112;

    __shared__ float As[16][132];   // padded to kill STS conflicts
    __shared__ float Bs[16][112];

    const int tid = threadIdx.x;
    const int tx  = tid & 15;       // n direction
    const int ty  = tid >> 4;       // m direction

    float acc[8][7];
    #pragma unroll
    for (int i = 0; i < 8; i++)
        #pragma unroll
        for (int j = 0; j < 7; j++) acc[i][j] = 0.f;

    const float* __restrict__ Xb = x + (size_t)b * CDIM * NPOS;

    for (int k0 = 0; k0 < CDIM; k0 += 16) {
        // A tile: 128 rows x 16 k, float4 per thread x2
        #pragma unroll
        for (int l = 0; l < 2; l++) {
            int t   = tid + l * 256;          // 0..511
            int row = t >> 2;
            int kq  = (t & 3) * 4;
            int gm  = m0 + row;
            const float* Wrow = (gm < CI) ? (Wth + (size_t)gm * CDIM)
                                          : (Wph + (size_t)(gm - CI) * CDIM);
            float4 v = *reinterpret_cast<const float4*>(Wrow + k0 + kq);
            As[kq + 0][row] = v.x;
            As[kq + 1][row] = v.y;
            As[kq + 2][row] = v.z;
            As[kq + 3][row] = v.w;
        }
        // B tile: 16 k-rows x 112 n, 7 scalars per thread
        #pragma unroll
        for (int l = 0; l < 7; l++) {
            int t  = tid + l * 256;           // 0..1791
            int kr = t / 112;
            int nc = t - kr * 112;
            Bs[kr][nc] = Xb[(size_t)(k0 + kr) * NPOS + n0 + nc];
        }
        __syncthreads();

        #pragma unroll
        for (int kk = 0; kk < 16; kk++) {
            float a[8], bb[7];
            #pragma unroll
            for (int i = 0; i < 8; i++) a[i] = As[kk][ty * 8 + i];
            #pragma unroll
            for (int j = 0; j < 7; j++) bb[j] = Bs[kk][tx * 7 + j];
            #pragma unroll
            for (int i = 0; i < 8; i++)
                #pragma unroll
                for (int j = 0; j < 7; j++)
                    acc[i][j] = fmaf(a[i], bb[j], acc[i][j]);
        }
        __syncthreads();
    }

    float* __restrict__ TPb = g_TP + (size_t)b * CDIM * NPOS;
    #pragma unroll
    for (int i = 0; i < 8; i++) {
        int gm = m0 + ty * 8 + i;
        float bias = (gm < CI) ? bth[gm] : bph[gm - CI];
        #pragma unroll
        for (int j = 0; j < 7; j++)
            TPb[(size_t)gm * NPOS + n0 + tx * 7 + j] = acc[i][j] + bias;
    }
}

// ===========================================================================
// GEMM2: F[b][n][m] = sum_k theta[k][n] * phi[k][m]   (k over 512)
//   theta = TP[b][k], phi = TP[b][512+k]; both K-major -> clean TN GEMM
//   tile 112(n) x 112(m) x 16(K), 256 threads, 7x7 per thread
// ===========================================================================
__global__ __launch_bounds__(256) void gemm2_kernel()
{
    const int b   = blockIdx.z;
    const int nb0 = blockIdx.y * 112;
    const int mb0 = blockIdx.x * 112;

    __shared__ float As[16][112];
    __shared__ float Bs[16][112];

    const int tid = threadIdx.x;
    const int tx  = tid & 15;
    const int ty  = tid >> 4;

    float acc[7][7];
    #pragma unroll
    for (int i = 0; i < 7; i++)
        #pragma unroll
        for (int j = 0; j < 7; j++) acc[i][j] = 0.f;

    const float* __restrict__ Th = g_TP + (size_t)b * CDIM * NPOS;
    const float* __restrict__ Ph = Th + (size_t)CI * NPOS;

    for (int k0 = 0; k0 < CI; k0 += 16) {
        #pragma unroll
        for (int l = 0; l < 7; l++) {
            int t  = tid + l * 256;
            int kr = t / 112;
            int c  = t - kr * 112;
            As[kr][c] = Th[(size_t)(k0 + kr) * NPOS + nb0 + c];
            Bs[kr][c] = Ph[(size_t)(k0 + kr) * NPOS + mb0 + c];
        }
        __syncthreads();

        #pragma unroll
        for (int kk = 0; kk < 16; kk++) {
            float a[7], bb[7];
            #pragma unroll
            for (int i = 0; i < 7; i++) a[i] = As[kk][ty * 7 + i];
            #pragma unroll
            for (int j = 0; j < 7; j++) bb[j] = Bs[kk][tx * 7 + j];
            #pragma unroll
            for (int i = 0; i < 7; i++)
                #pragma unroll
                for (int j = 0; j < 7; j++)
                    acc[i][j] = fmaf(a[i], bb[j], acc[i][j]);
        }
        __syncthreads();
    }

    float* __restrict__ Fb = g_F + (size_t)b * NPOS * NPOS;
    #pragma unroll
    for (int i = 0; i < 7; i++)
        #pragma unroll
        for (int j = 0; j < 7; j++)
            Fb[(size_t)(nb0 + ty * 7 + i) * NPOS + mb0 + tx * 7 + j] = acc[i][j];
}

// ===========================================================================
// Row softmax stats: per row compute max, overwrite F with exp(f - max),
// store rscale = 1/(rowsum * N).
// ===========================================================================
__global__ __launch_bounds__(256) void softmax_row_kernel()
{
    const int b = blockIdx.y;
    const int n = blockIdx.x;
    float* __restrict__ row = g_F + ((size_t)b * NPOS + n) * NPOS;
    const int tid = threadIdx.x;

    __shared__ float red[8];
    __shared__ float smax;

    float m = -CUDART_INF_F;
    for (int i = tid; i < NPOS; i += 256) m = fmaxf(m, row[i]);
    #pragma unroll
    for (int o = 16; o; o >>= 1) m = fmaxf(m, __shfl_xor_sync(0xffffffffu, m, o));
    if ((tid & 31) == 0) red[tid >> 5] = m;
    __syncthreads();
    if (tid == 0) {
        float v = red[0];
        #pragma unroll
        for (int i = 1; i < 8; i++) v = fmaxf(v, red[i]);
        smax = v;
    }
    __syncthreads();
    float bm = smax;

    float s = 0.f;
    for (int i = tid; i < NPOS; i += 256) {
        float e = __expf(row[i] - bm);
        row[i] = e;
        s += e;
    }
    #pragma unroll
    for (int o = 16; o; o >>= 1) s += __shfl_xor_sync(0xffffffffu, s, o);
    if ((tid & 31) == 0) red[tid >> 5] = s;
    __syncthreads();
    if (tid == 0) {
        float v = 0.f;
        #pragma unroll
        for (int i = 0; i < 8; i++) v += red[i];
        g_rscale[b * NPOS + n] = 1.f / (v * (float)NPOS);
    }
}

__global__ __launch_bounds__(256) void zero_abar_kernel()
{
    int i = blockIdx.x * 256 + threadIdx.x;
    if (i < BATCH * NPOS) g_abar[i] = 0.f;
}

// a_bar[b][m] = sum_n E[n][m] * rscale[n]   (partials over 98-row chunks, atomic)
__global__ __launch_bounds__(112) void colsum_kernel()
{
    const int b  = blockIdx.z;
    const int m  = blockIdx.x * 112 + threadIdx.x;
    const int n0 = blockIdx.y * 98;

    __shared__ float srs[98];
    for (int i = threadIdx.x; i < 98; i += 112) srs[i] = g_rscale[b * NPOS + n0 + i];
    __syncthreads();

    const float* __restrict__ Fb = g_F + (size_t)b * NPOS * NPOS;
    float acc = 0.f;
    #pragma unroll 2
    for (int j = 0; j < 98; j++)
        acc += Fb[(size_t)(n0 + j) * NPOS + m] * srs[j];
    atomicAdd(&g_abar[b * NPOS + m], acc);
}

// xw[b][c] = X[b][c][:] . a_bar[b][:] ; xbar[b][c] = mean_n X
__global__ __launch_bounds__(256) void xw_kernel(const float* __restrict__ x)
{
    const int b    = blockIdx.y;
    const int c    = blockIdx.x * 8 + (threadIdx.x >> 5);
    const int lane = threadIdx.x & 31;

    __shared__ float sa[NPOS];
    for (int i = threadIdx.x; i < NPOS; i += 256) sa[i] = g_abar[b * NPOS + i];
    __syncthreads();

    const float* __restrict__ xr = x + ((size_t)b * CDIM + c) * NPOS;
    float dot = 0.f, sum = 0.f;
    for (int i = lane; i < NPOS; i += 32) {
        float v = xr[i];
        dot = fmaf(v, sa[i], dot);
        sum += v;
    }
    #pragma unroll
    for (int o = 16; o; o >>= 1) {
        dot += __shfl_xor_sync(0xffffffffu, dot, o);
        sum += __shfl_xor_sync(0xffffffffu, sum, o);
    }
    if (lane == 0) {
        g_xw[b * CDIM + c]   = dot;
        g_xbar[b * CDIM + c] = sum * (1.f / (float)NPOS);
    }
}

// ybar[b][i] = Wg[i][:] . xw[b][:] + bg[i]
__global__ __launch_bounds__(256) void ybar_kernel(const float* __restrict__ Wg,
                                                   const float* __restrict__ bg)
{
    const int b    = blockIdx.y;
    const int i    = blockIdx.x * 8 + (threadIdx.x >> 5);
    const int lane = threadIdx.x & 31;

    __shared__ float sx[CDIM];
    for (int k = threadIdx.x; k < CDIM; k += 256) sx[k] = g_xw[b * CDIM + k];
    __syncthreads();

    const float* __restrict__ w = Wg + (size_t)i * CDIM;
    float d = 0.f;
    for (int k = lane; k < CDIM; k += 32) d = fmaf(w[k], sx[k], d);
    #pragma unroll
    for (int o = 16; o; o >>= 1) d += __shfl_xor_sync(0xffffffffu, d, o);
    if (lane == 0) g_ybar[b * CI + i] = d + bg[i];
}

// pooled[b][c] = inv[c]*(Ww[c][:].ybar[b][:] + bw[c]) + (beta - mean*inv)[c] + xbar[b][c]
__global__ __launch_bounds__(256) void pooled_kernel(
    const float* __restrict__ Ww, const float* __restrict__ bw,
    const float* __restrict__ gamma, const float* __restrict__ beta,
    const float* __restrict__ bmean, const float* __restrict__ bvar)
{
    const int b    = blockIdx.y;
    const int c    = blockIdx.x * 8 + (threadIdx.x >> 5);
    const int lane = threadIdx.x & 31;

    __shared__ float sy[CI];
    for (int k = threadIdx.x; k < CI; k += 256) sy[k] = g_ybar[b * CI + k];
    __syncthreads();

    const float* __restrict__ w = Ww + (size_t)c * CI;
    float d = 0.f;
    for (int k = lane; k < CI; k += 32) d = fmaf(w[k], sy[k], d);
    #pragma unroll
    for (int o = 16; o; o >>= 1) d += __shfl_xor_sync(0xffffffffu, d, o);
    if (lane == 0) {
        float inv = gamma[c] * rsqrtf(bvar[c] + 1e-5f);
        g_pooled[b * CDIM + c] =
            inv * (d + bw[c]) + (beta[c] - bmean[c] * inv) + g_xbar[b * CDIM + c];
    }
}

// h[b][j] = W1[j][:] . pooled[b][:] + b1[j]
__global__ __launch_bounds__(256) void h_kernel(const float* __restrict__ W1,
                                                const float* __restrict__ b1)
{
    const int b    = blockIdx.y;
    const int j    = blockIdx.x * 8 + (threadIdx.x >> 5);
    const int lane = threadIdx.x & 31;

    __shared__ float sp[CDIM];
    for (int k = threadIdx.x; k < CDIM; k += 256) sp[k] = g_pooled[b * CDIM + k];
    __syncthreads();

    const float* __restrict__ w = W1 + (size_t)j * CDIM;
    float d = 0.f;
    for (int k = lane; k < CDIM; k += 32) d = fmaf(w[k], sp[k], d);
    #pragma unroll
    for (int o = 16; o; o >>= 1) d += __shfl_xor_sync(0xffffffffu, d, o);
    if (lane == 0) g_h[b * CI + j] = d + b1[j];
}

// out[b][o] = W2[o][0:512].h[b] + W2[o][512:1024].x_face[b] + b2[o]
__global__ __launch_bounds__(256) void out_kernel(const float* __restrict__ xface,
                                                  const float* __restrict__ W2,
                                                  const float* __restrict__ b2,
                                                  float* __restrict__ out)
{
    const int b = blockIdx.x;
    const int o = threadIdx.x >> 7;      // 0 or 1
    const int t = threadIdx.x & 127;

    float acc = 0.f;
    for (int k = t; k < CDIM; k += 128) {
        float v = (k < CI) ? g_h[b * CI + k] : xface[b * CI + (k - CI)];
        acc = fmaf(W2[o * CDIM + k], v, acc);
    }
    #pragma unroll
    for (int off = 16; off; off >>= 1) acc += __shfl_xor_sync(0xffffffffu, acc, off);

    __shared__ float sred[8];
    const int warp = threadIdx.x >> 5;
    if ((threadIdx.x & 31) == 0) sred[warp] = acc;
    __syncthreads();
    if (threadIdx.x == 0)
        out[b * 2 + 0] = sred[0] + sred[1] + sred[2] + sred[3] + b2[0];
    if (threadIdx.x == 128)
        out[b * 2 + 1] = sred[4] + sred[5] + sred[6] + sred[7] + b2[1];
}

// ===========================================================================
extern "C" void kernel_launch(void* const* d_in, const int* in_sizes, int n_in,
                              void* d_out, int out_size)
{
    const float* x_body = (const float*)d_in[0];
    const float* x_face = (const float*)d_in[1];
    const float* Wg     = (const float*)d_in[2];
    const float* bg     = (const float*)d_in[3];
    const float* Wth    = (const float*)d_in[4];
    const float* bth    = (const float*)d_in[5];
    const float* Wph    = (const float*)d_in[6];
    const float* bph    = (const float*)d_in[7];
    const float* Ww     = (const float*)d_in[8];
    const float* bw     = (const float*)d_in[9];
    const float* gamma  = (const float*)d_in[10];
    const float* beta   = (const float*)d_in[11];
    const float* bmean  = (const float*)d_in[12];
    const float* bvar   = (const float*)d_in[13];
    const float* W1     = (const float*)d_in[14];
    const float* b1     = (const float*)d_in[15];
    const float* W2     = (const float*)d_in[16];
    const float* b2     = (const float*)d_in[17];
    float* out = (float*)d_out;

    zero_abar_kernel<<<(BATCH * NPOS + 255) / 256, 256>>>();

    // theta+phi projection (fused, one pass over X)
    gemm1_kernel<<<dim3(NPOS / 112, CDIM / 128, BATCH), 256>>>(x_body, Wth, bth, Wph, bph);

    // f = theta^T phi
    gemm2_kernel<<<dim3(NPOS / 112, NPOS / 112, BATCH), 256>>>();

    // softmax stats (F overwritten with exp(f - rowmax))
    softmax_row_kernel<<<dim3(NPOS, BATCH), 256>>>();

    // column means of attn
    colsum_kernel<<<dim3(NPOS / 112, 8, BATCH), 112>>>();

    // xw = X @ a_bar, xbar = mean_n X
    xw_kernel<<<dim3(CDIM / 8, BATCH), 256>>>(x_body);

    // ybar = Wg @ xw + bg
    ybar_kernel<<<dim3(CI / 8, BATCH), 256>>>(Wg, bg);

    // pooled = BN(Ww @ ybar + bw) + xbar
    pooled_kernel<<<dim3(CDIM / 8, BATCH), 256>>>(Ww, bw, gamma, beta, bmean, bvar);

    // FC head
    h_kernel<<<dim3(CI / 8, BATCH), 256>>>(W1, b1);
    out_kernel<<<BATCH, 256>>>(x_face, W2, b2, out);
}

// round 3
// speedup vs baseline: 2.5309x; 2.5309x over previous
#include <cuda_runtime.h>
#include <cuda_bf16.h>
#include <math_constants.h>
#include <cstdint>

#define BATCH 32
#define CDIM  1024
#define CI    512
#define NPOS  784

// -------- scratch (device globals) --------
__device__ __align__(16) __nv_bfloat16 g_Wh[(size_t)CDIM * CDIM];
__device__ __align__(16) __nv_bfloat16 g_Wl[(size_t)CDIM * CDIM];
__device__ __align__(16) __nv_bfloat16 g_Xth[(size_t)BATCH * NPOS * CDIM];  // X^T hi [b][n][c]
__device__ __align__(16) __nv_bfloat16 g_Xtl[(size_t)BATCH * NPOS * CDIM];  // X^T lo
__device__ __align__(16) __nv_bfloat16 g_Tth[(size_t)BATCH * NPOS * CI];    // theta^T hi [b][n][k]
__device__ __align__(16) __nv_bfloat16 g_Ttl[(size_t)BATCH * NPOS * CI];
__device__ __align__(16) __nv_bfloat16 g_Pth[(size_t)BATCH * NPOS * CI];    // phi^T hi
__device__ __align__(16) __nv_bfloat16 g_Ptl[(size_t)BATCH * NPOS * CI];
__device__ __align__(16) float g_F[(size_t)BATCH * NPOS * NPOS];            // raw logits
__device__ float g_rmax[BATCH * NPOS];
__device__ float g_rscale[BATCH * NPOS];
__device__ float g_abar[BATCH * NPOS];
__device__ float g_xw[BATCH * CDIM];
__device__ float g_xbar[BATCH * CDIM];
__device__ float g_ybar[BATCH * CI];
__device__ float g_pooled[BATCH * CDIM];
__device__ float g_h[BATCH * CI];

// -------- helpers --------
__device__ __forceinline__ uint32_t smem_u32(const void* p) {
    uint32_t a;
    asm("{ .reg .u64 t; cvta.to.shared.u64 t, %1; cvt.u32.u64 %0, t; }" : "=r"(a) : "l"(p));
    return a;
}
__device__ __forceinline__ void cp16(uint32_t dst, const void* src) {
    asm volatile("cp.async.cg.shared.global [%0], [%1], 16;" :: "r"(dst), "l"(src) : "memory");
}
#define CP_COMMIT() asm volatile("cp.async.commit_group;" ::: "memory")
#define CP_WAIT_1() asm volatile("cp.async.wait_group 1;" ::: "memory")

__device__ __forceinline__ void ldsm_x4(uint32_t (&r)[4], uint32_t a) {
    asm volatile("ldmatrix.sync.aligned.m8n8.x4.shared.b16 {%0,%1,%2,%3}, [%4];"
                 : "=r"(r[0]), "=r"(r[1]), "=r"(r[2]), "=r"(r[3]) : "r"(a));
}
__device__ __forceinline__ void ldsm_x2(uint32_t& r0, uint32_t& r1, uint32_t a) {
    asm volatile("ldmatrix.sync.aligned.m8n8.x2.shared.b16 {%0,%1}, [%2];"
                 : "=r"(r0), "=r"(r1) : "r"(a));
}
__device__ __forceinline__ void mma16816(float* c, const uint32_t* a, const uint32_t* b) {
    asm volatile(
        "mma.sync.aligned.m16n8k16.row.col.f32.bf16.bf16.f32 "
        "{%0,%1,%2,%3}, {%4,%5,%6,%7}, {%8,%9}, {%0,%1,%2,%3};"
        : "+f"(c[0]), "+f"(c[1]), "+f"(c[2]), "+f"(c[3])
        : "r"(a[0]), "r"(a[1]), "r"(a[2]), "r"(a[3]), "r"(b[0]), "r"(b[1]));
}

// ===========================================================================
// conversion: fp32 -> bf16 hi/lo
// ===========================================================================
__global__ __launch_bounds__(256) void convert_W_kernel(
    const float* __restrict__ Wth, const float* __restrict__ Wph)
{
    int i = blockIdx.x * 256 + threadIdx.x;
    float w = (i < CI * CDIM) ? Wth[i] : Wph[i - CI * CDIM];
    __nv_bfloat16 hi = __float2bfloat16(w);
    g_Wh[i] = hi;
    g_Wl[i] = __float2bfloat16(w - __bfloat162float(hi));
}

__global__ __launch_bounds__(256) void convert_X_kernel(const float* __restrict__ x)
{
    __shared__ float tile[32][33];
    const int b  = blockIdx.z;
    const int c0 = blockIdx.y * 32;
    const int n0 = blockIdx.x * 32;
    const int tx = threadIdx.x & 31;
    const int ty = threadIdx.x >> 5;

    #pragma unroll
    for (int i = 0; i < 4; i++) {
        int c = c0 + ty + i * 8;
        int n = n0 + tx;
        tile[ty + i * 8][tx] = (n < NPOS) ? x[((size_t)b * CDIM + c) * NPOS + n] : 0.f;
    }
    __syncthreads();
    #pragma unroll
    for (int i = 0; i < 4; i++) {
        int n = n0 + ty + i * 8;
        int c = c0 + tx;
        if (n < NPOS) {
            float v = tile[tx][ty + i * 8];
            __nv_bfloat16 hi = __float2bfloat16(v);
            size_t o = ((size_t)b * NPOS + n) * CDIM + c;
            g_Xth[o] = hi;
            g_Xtl[o] = __float2bfloat16(v - __bfloat162float(hi));
        }
    }
}

// ===========================================================================
// GEMM1 (warp MMA): C[m][n] = sum_k W[m][k] X^T[n][k],  m tile 128, n tile 112
// hi/lo 3-product. Epilogue: +bias, transpose, bf16 hi/lo store to theta/phi.
// ===========================================================================
#define G1_ASPL  10240           // 128 rows * 80B
#define G1_BOFF  20480
#define G1_BSPL  8960            // 112 rows * 80B
#define G1_STAGE 38400
#define G1_SMEM  76800

__global__ __launch_bounds__(256, 2) void gemm1_mma(
    const float* __restrict__ bth, const float* __restrict__ bph)
{
    extern __shared__ char smc[];
    const uint32_t sbase = smem_u32(smc);
    const int tid  = threadIdx.x;
    const int lane = tid & 31;
    const int wid  = tid >> 5;
    const int wm   = wid >> 1;           // 0..3  (M)
    const int wn   = wid & 1;            // 0..1  (N)
    const int b    = blockIdx.z;
    const int m0   = blockIdx.y * 128;
    const int n0   = blockIdx.x * 112;

    float acc[14][4];
    #pragma unroll
    for (int i = 0; i < 14; i++)
        #pragma unroll
        for (int j = 0; j < 4; j++) acc[i][j] = 0.f;

    auto issue = [&](int kt, int buf) {
        const int k0 = kt * 32;
        const uint32_t st = sbase + buf * G1_STAGE;
        #pragma unroll
        for (int i = 0; i < 4; i++) {           // A: 1024 tasks of 16B
            int t = tid + i * 256;
            int split = t >> 9, idx = t & 511, row = idx >> 2, ch = idx & 3;
            const __nv_bfloat16* src = (split ? g_Wl : g_Wh)
                + (size_t)(m0 + row) * CDIM + k0 + ch * 8;
            cp16(st + split * G1_ASPL + row * 80 + ch * 16, src);
        }
        #pragma unroll
        for (int i = 0; i < 4; i++) {           // B: 896 tasks
            int t = tid + i * 256;
            if (t < 896) {
                int split = (t >= 448);
                int idx = t - split * 448, row = idx >> 2, ch = idx & 3;
                const __nv_bfloat16* src = (split ? g_Xtl : g_Xth)
                    + ((size_t)b * NPOS + n0 + row) * CDIM + k0 + ch * 8;
                cp16(st + G1_BOFF + split * G1_BSPL + row * 80 + ch * 16, src);
            }
        }
        CP_COMMIT();
    };

    issue(0, 0);
    issue(1, 1);

    const int arow = lane & 15;
    const int ach  = lane >> 4;
    const int brow = ((lane >> 4) << 3) + (lane & 7);
    const int bch  = (lane >> 3) & 1;
    const int brow2 = (lane & 15) & 7;
    const int bch2  = ((lane & 15) >> 3) & 1;

    for (int kt = 0; kt < 32; kt++) {
        CP_WAIT_1();
        __syncthreads();
        const uint32_t st = sbase + (kt & 1) * G1_STAGE;
        #pragma unroll
        for (int s = 0; s < 2; s++) {
            uint32_t ah[2][4], al[2][4], bb[7][2];
            #pragma unroll
            for (int i = 0; i < 2; i++) {
                uint32_t aa = st + (wm * 32 + i * 16 + arow) * 80 + (s * 2 + ach) * 16;
                ldsm_x4(ah[i], aa);
                ldsm_x4(al[i], aa + G1_ASPL);
            }
            #pragma unroll
            for (int p = 0; p < 3; p++) {
                uint32_t ba = st + G1_BOFF + (wn * 56 + p * 16 + brow) * 80 + (s * 2 + bch) * 16;
                uint32_t r[4]; ldsm_x4(r, ba);
                bb[p*2][0] = r[0]; bb[p*2][1] = r[1];
                bb[p*2+1][0] = r[2]; bb[p*2+1][1] = r[3];
            }
            ldsm_x2(bb[6][0], bb[6][1],
                    st + G1_BOFF + (wn * 56 + 48 + brow2) * 80 + (s * 2 + bch2) * 16);
            #pragma unroll
            for (int i = 0; i < 2; i++)
                #pragma unroll
                for (int j = 0; j < 7; j++) {
                    mma16816(acc[i*7+j], ah[i], bb[j]);   // Ah*Bh
                    mma16816(acc[i*7+j], al[i], bb[j]);   // Al*Bh
                }
            #pragma unroll
            for (int p = 0; p < 3; p++) {
                uint32_t ba = st + G1_BOFF + G1_BSPL
                            + (wn * 56 + p * 16 + brow) * 80 + (s * 2 + bch) * 16;
                uint32_t r[4]; ldsm_x4(r, ba);
                bb[p*2][0] = r[0]; bb[p*2][1] = r[1];
                bb[p*2+1][0] = r[2]; bb[p*2+1][1] = r[3];
            }
            ldsm_x2(bb[6][0], bb[6][1],
                    st + G1_BOFF + G1_BSPL + (wn * 56 + 48 + brow2) * 80 + (s * 2 + bch2) * 16);
            #pragma unroll
            for (int i = 0; i < 2; i++)
                #pragma unroll
                for (int j = 0; j < 7; j++)
                    mma16816(acc[i*7+j], ah[i], bb[j]);   // Ah*Bl
        }
        __syncthreads();
        if (kt + 2 < 32) issue(kt + 2, kt & 1); else CP_COMMIT();
    }

    // ---- epilogue: smem bounce [ch][n] pitch 113, then transposed hi/lo store
    __syncthreads();
    float* eb = reinterpret_cast<float*>(smc);
    #pragma unroll
    for (int i = 0; i < 2; i++)
        #pragma unroll
        for (int j = 0; j < 7; j++) {
            int row = wm * 32 + i * 16 + (lane >> 2);
            int col = wn * 56 + j * 8 + (lane & 3) * 2;
            eb[row * 113 + col]           = acc[i*7+j][0];
            eb[row * 113 + col + 1]       = acc[i*7+j][1];
            eb[(row + 8) * 113 + col]     = acc[i*7+j][2];
            eb[(row + 8) * 113 + col + 1] = acc[i*7+j][3];
        }
    __syncthreads();

    const bool isTheta = (m0 < CI);
    __nv_bfloat16* dhi = isTheta ? g_Tth : g_Pth;
    __nv_bfloat16* dlo = isTheta ? g_Ttl : g_Ptl;
    const int ch0g = isTheta ? m0 : (m0 - CI);
    const float* bias = isTheta ? bth : bph;

    #pragma unroll
    for (int it = 0; it < 7; it++) {
        int t  = tid + it * 256;       // 0..1791
        int cg = t & 15, n = t >> 4;
        int chl = cg * 8;
        __align__(16) __nv_bfloat16 h8[8], l8[8];
        #pragma unroll
        for (int k = 0; k < 8; k++) {
            float v = eb[(chl + k) * 113 + n] + bias[ch0g + chl + k];
            __nv_bfloat16 hv = __float2bfloat16(v);
            h8[k] = hv;
            l8[k] = __float2bfloat16(v - __bfloat162float(hv));
        }
        size_t off = ((size_t)b * NPOS + n0 + n) * CI + ch0g + chl;
        *reinterpret_cast<uint4*>(dhi + off) = *reinterpret_cast<const uint4*>(h8);
        *reinterpret_cast<uint4*>(dlo + off) = *reinterpret_cast<const uint4*>(l8);
    }
}

// ===========================================================================
// GEMM2 (warp MMA): F[n][m] = sum_k theta^T[n][k] phi^T[m][k]
// tile 112x112xK512, 7 warps (warp = one m16 row-tile, all 112 cols)
// ===========================================================================
#define G2_ASPL  8960
#define G2_BOFF  17920
#define G2_BSPL  8960
#define G2_STAGE 35840
#define G2_SMEM  71680

__global__ __launch_bounds__(224, 2) void gemm2_mma()
{
    extern __shared__ char smc[];
    const uint32_t sbase = smem_u32(smc);
    const int tid  = threadIdx.x;
    const int lane = tid & 31;
    const int wid  = tid >> 5;           // 0..6
    const int b    = blockIdx.z;
    const int n0   = blockIdx.y * 112;   // rows (theta)
    const int mb0  = blockIdx.x * 112;   // cols (phi)

    float acc[14][4];
    #pragma unroll
    for (int i = 0; i < 14; i++)
        #pragma unroll
        for (int j = 0; j < 4; j++) acc[i][j] = 0.f;

    auto issue = [&](int kt, int buf) {
        const int k0 = kt * 32;
        const uint32_t st = sbase + buf * G2_STAGE;
        #pragma unroll
        for (int i = 0; i < 4; i++) {
            int t = tid + i * 224;       // 0..895
            int split = (t >= 448);
            int idx = t - split * 448, row = idx >> 2, ch = idx & 3;
            const __nv_bfloat16* asrc = (split ? g_Ttl : g_Tth)
                + ((size_t)b * NPOS + n0 + row) * CI + k0 + ch * 8;
            cp16(st + split * G2_ASPL + row * 80 + ch * 16, asrc);
            const __nv_bfloat16* bsrc = (split ? g_Ptl : g_Pth)
                + ((size_t)b * NPOS + mb0 + row) * CI + k0 + ch * 8;
            cp16(st + G2_BOFF + split * G2_BSPL + row * 80 + ch * 16, bsrc);
        }
        CP_COMMIT();
    };

    issue(0, 0);
    issue(1, 1);

    const int arow = lane & 15;
    const int ach  = lane >> 4;
    const int brow = ((lane >> 4) << 3) + (lane & 7);
    const int bch  = (lane >> 3) & 1;

    for (int kt = 0; kt < 16; kt++) {
        CP_WAIT_1();
        __syncthreads();
        const uint32_t st = sbase + (kt & 1) * G2_STAGE;
        #pragma unroll
        for (int s = 0; s < 2; s++) {
            uint32_t ah[4], al[4], bb[14][2];
            uint32_t aa = st + (wid * 16 + arow) * 80 + (s * 2 + ach) * 16;
            ldsm_x4(ah, aa);
            ldsm_x4(al, aa + G2_ASPL);
            #pragma unroll
            for (int p = 0; p < 7; p++) {
                uint32_t ba = st + G2_BOFF + (p * 16 + brow) * 80 + (s * 2 + bch) * 16;
                uint32_t r[4]; ldsm_x4(r, ba);
                bb[p*2][0] = r[0]; bb[p*2][1] = r[1];
                bb[p*2+1][0] = r[2]; bb[p*2+1][1] = r[3];
            }
            #pragma unroll
            for (int j = 0; j < 14; j++) {
                mma16816(acc[j], ah, bb[j]);
                mma16816(acc[j], al, bb[j]);
            }
            #pragma unroll
            for (int p = 0; p < 7; p++) {
                uint32_t ba = st + G2_BOFF + G2_BSPL + (p * 16 + brow) * 80 + (s * 2 + bch) * 16;
                uint32_t r[4]; ldsm_x4(r, ba);
                bb[p*2][0] = r[0]; bb[p*2][1] = r[1];
                bb[p*2+1][0] = r[2]; bb[p*2+1][1] = r[3];
            }
            #pragma unroll
            for (int j = 0; j < 14; j++)
                mma16816(acc[j], ah, bb[j]);
        }
        __syncthreads();
        if (kt + 2 < 16) issue(kt + 2, kt & 1); else CP_COMMIT();
    }

    // epilogue: smem bounce [112][116], coalesced float4 stores
    __syncthreads();
    float* eb = reinterpret_cast<float*>(smc);
    #pragma unroll
    for (int j = 0; j < 14; j++) {
        int row = wid * 16 + (lane >> 2);
        int col = j * 8 + (lane & 3) * 2;
        eb[row * 116 + col]           = acc[j][0];
        eb[row * 116 + col + 1]       = acc[j][1];
        eb[(row + 8) * 116 + col]     = acc[j][2];
        eb[(row + 8) * 116 + col + 1] = acc[j][3];
    }
    __syncthreads();
    #pragma unroll
    for (int i = 0; i < 14; i++) {
        int t = tid + i * 224;          // 0..3135
        int row = t / 28, c4 = t % 28;
        float4 v = *reinterpret_cast<const float4*>(&eb[row * 116 + c4 * 4]);
        *reinterpret_cast<float4*>(g_F + ((size_t)b * NPOS + n0 + row) * NPOS + mb0 + c4 * 4) = v;
    }
}

// ===========================================================================
// softmax stats: per-row max and 1/(sum*N)
// ===========================================================================
__global__ __launch_bounds__(256) void softmax_stats_kernel()
{
    const int b = blockIdx.y;
    const int n = blockIdx.x;
    const float* __restrict__ row = g_F + ((size_t)b * NPOS + n) * NPOS;
    const int tid = threadIdx.x;

    __shared__ float srow[NPOS];
    __shared__ float red[8];
    __shared__ float smax;

    float m = -CUDART_INF_F;
    const float4* row4 = reinterpret_cast<const float4*>(row);
    for (int i = tid; i < NPOS / 4; i += 256) {
        float4 v = row4[i];
        srow[i * 4 + 0] = v.x; srow[i * 4 + 1] = v.y;
        srow[i * 4 + 2] = v.z; srow[i * 4 + 3] = v.w;
        m = fmaxf(m, fmaxf(fmaxf(v.x, v.y), fmaxf(v.z, v.w)));
    }
    #pragma unroll
    for (int o = 16; o; o >>= 1) m = fmaxf(m, __shfl_xor_sync(0xffffffffu, m, o));
    if ((tid & 31) == 0) red[tid >> 5] = m;
    __syncthreads();
    if (tid == 0) {
        float v = red[0];
        #pragma unroll
        for (int i = 1; i < 8; i++) v = fmaxf(v, red[i]);
        smax = v;
    }
    __syncthreads();
    const float bm = smax;

    float s = 0.f;
    for (int i = tid; i < NPOS; i += 256) s += __expf(srow[i] - bm);
    #pragma unroll
    for (int o = 16; o; o >>= 1) s += __shfl_xor_sync(0xffffffffu, s, o);
    if ((tid & 31) == 0) red[tid >> 5] = s;
    __syncthreads();
    if (tid == 0) {
        float v = 0.f;
        #pragma unroll
        for (int i = 0; i < 8; i++) v += red[i];
        g_rmax[b * NPOS + n]   = bm;
        g_rscale[b * NPOS + n] = 1.f / (v * (float)NPOS);
    }
}

__global__ __launch_bounds__(256) void zero_abar_kernel()
{
    int i = blockIdx.x * 256 + threadIdx.x;
    if (i < BATCH * NPOS) g_abar[i] = 0.f;
}

// a_bar[b][m] = sum_n exp(F[n][m]-rmax[n]) * rscale[n]
__global__ __launch_bounds__(112) void colsum_kernel()
{
    const int b  = blockIdx.z;
    const int m  = blockIdx.x * 112 + threadIdx.x;
    const int n0 = blockIdx.y * 98;

    __shared__ float srs[98];
    __shared__ float smx[98];
    for (int i = threadIdx.x; i < 98; i += 112) {
        srs[i] = g_rscale[b * NPOS + n0 + i];
        smx[i] = g_rmax[b * NPOS + n0 + i];
    }
    __syncthreads();

    const float* __restrict__ Fb = g_F + (size_t)b * NPOS * NPOS;
    float acc = 0.f;
    #pragma unroll 2
    for (int j = 0; j < 98; j++)
        acc += __expf(Fb[(size_t)(n0 + j) * NPOS + m] - smx[j]) * srs[j];
    atomicAdd(&g_abar[b * NPOS + m], acc);
}

__global__ __launch_bounds__(256) void xw_kernel(const float* __restrict__ x)
{
    const int b    = blockIdx.y;
    const int c    = blockIdx.x * 8 + (threadIdx.x >> 5);
    const int lane = threadIdx.x & 31;

    __shared__ float sa[NPOS];
    for (int i = threadIdx.x; i < NPOS; i += 256) sa[i] = g_abar[b * NPOS + i];
    __syncthreads();

    const float* __restrict__ xr = x + ((size_t)b * CDIM + c) * NPOS;
    float dot = 0.f, sum = 0.f;
    for (int i = lane; i < NPOS; i += 32) {
        float v = xr[i];
        dot = fmaf(v, sa[i], dot);
        sum += v;
    }
    #pragma unroll
    for (int o = 16; o; o >>= 1) {
        dot += __shfl_xor_sync(0xffffffffu, dot, o);
        sum += __shfl_xor_sync(0xffffffffu, sum, o);
    }
    if (lane == 0) {
        g_xw[b * CDIM + c]   = dot;
        g_xbar[b * CDIM + c] = sum * (1.f / (float)NPOS);
    }
}

__global__ __launch_bounds__(256) void ybar_kernel(const float* __restrict__ Wg,
                                                   const float* __restrict__ bg)
{
    const int b    = blockIdx.y;
    const int i    = blockIdx.x * 8 + (threadIdx.x >> 5);
    const int lane = threadIdx.x & 31;

    __shared__ float sx[CDIM];
    for (int k = threadIdx.x; k < CDIM; k += 256) sx[k] = g_xw[b * CDIM + k];
    __syncthreads();

    const float* __restrict__ w = Wg + (size_t)i * CDIM;
    float d = 0.f;
    for (int k = lane; k < CDIM; k += 32) d = fmaf(w[k], sx[k], d);
    #pragma unroll
    for (int o = 16; o; o >>= 1) d += __shfl_xor_sync(0xffffffffu, d, o);
    if (lane == 0) g_ybar[b * CI + i] = d + bg[i];
}

__global__ __launch_bounds__(256) void pooled_kernel(
    const float* __restrict__ Ww, const float* __restrict__ bw,
    const float* __restrict__ gamma, const float* __restrict__ beta,
    const float* __restrict__ bmean, const float* __restrict__ bvar)
{
    const int b    = blockIdx.y;
    const int c    = blockIdx.x * 8 + (threadIdx.x >> 5);
    const int lane = threadIdx.x & 31;

    __shared__ float sy[CI];
    for (int k = threadIdx.x; k < CI; k += 256) sy[k] = g_ybar[b * CI + k];
    __syncthreads();

    const float* __restrict__ w = Ww + (size_t)c * CI;
    float d = 0.f;
    for (int k = lane; k < CI; k += 32) d = fmaf(w[k], sy[k], d);
    #pragma unroll
    for (int o = 16; o; o >>= 1) d += __shfl_xor_sync(0xffffffffu, d, o);
    if (lane == 0) {
        float inv = gamma[c] * rsqrtf(bvar[c] + 1e-5f);
        g_pooled[b * CDIM + c] =
            inv * (d + bw[c]) + (beta[c] - bmean[c] * inv) + g_xbar[b * CDIM + c];
    }
}

__global__ __launch_bounds__(256) void h_kernel(const float* __restrict__ W1,
                                                const float* __restrict__ b1)
{
    const int b    = blockIdx.y;
    const int j    = blockIdx.x * 8 + (threadIdx.x >> 5);
    const int lane = threadIdx.x & 31;

    __shared__ float sp[CDIM];
    for (int k = threadIdx.x; k < CDIM; k += 256) sp[k] = g_pooled[b * CDIM + k];
    __syncthreads();

    const float* __restrict__ w = W1 + (size_t)j * CDIM;
    float d = 0.f;
    for (int k = lane; k < CDIM; k += 32) d = fmaf(w[k], sp[k], d);
    #pragma unroll
    for (int o = 16; o; o >>= 1) d += __shfl_xor_sync(0xffffffffu, d, o);
    if (lane == 0) g_h[b * CI + j] = d + b1[j];
}

__global__ __launch_bounds__(256) void out_kernel(const float* __restrict__ xface,
                                                  const float* __restrict__ W2,
                                                  const float* __restrict__ b2,
                                                  float* __restrict__ out)
{
    const int b = blockIdx.x;
    const int o = threadIdx.x >> 7;
    const int t = threadIdx.x & 127;

    float acc = 0.f;
    for (int k = t; k < CDIM; k += 128) {
        float v = (k < CI) ? g_h[b * CI + k] : xface[b * CI + (k - CI)];
        acc = fmaf(W2[o * CDIM + k], v, acc);
    }
    #pragma unroll
    for (int off = 16; off; off >>= 1) acc += __shfl_xor_sync(0xffffffffu, acc, off);

    __shared__ float sred[8];
    const int warp = threadIdx.x >> 5;
    if ((threadIdx.x & 31) == 0) sred[warp] = acc;
    __syncthreads();
    if (threadIdx.x == 0)
        out[b * 2 + 0] = sred[0] + sred[1] + sred[2] + sred[3] + b2[0];
    if (threadIdx.x == 128)
        out[b * 2 + 1] = sred[4] + sred[5] + sred[6] + sred[7] + b2[1];
}

// ===========================================================================
extern "C" void kernel_launch(void* const* d_in, const int* in_sizes, int n_in,
                              void* d_out, int out_size)
{
    const float* x_body = (const float*)d_in[0];
    const float* x_face = (const float*)d_in[1];
    const float* Wg     = (const float*)d_in[2];
    const float* bg     = (const float*)d_in[3];
    const float* Wth    = (const float*)d_in[4];
    const float* bth    = (const float*)d_in[5];
    const float* Wph    = (const float*)d_in[6];
    const float* bph    = (const float*)d_in[7];
    const float* Ww     = (const float*)d_in[8];
    const float* bw     = (const float*)d_in[9];
    const float* gamma  = (const float*)d_in[10];
    const float* beta   = (const float*)d_in[11];
    const float* bmean  = (const float*)d_in[12];
    const float* bvar   = (const float*)d_in[13];
    const float* W1     = (const float*)d_in[14];
    const float* b1     = (const float*)d_in[15];
    const float* W2     = (const float*)d_in[16];
    const float* b2     = (const float*)d_in[17];
    float* out = (float*)d_out;

    static bool attr_done = false;
    cudaFuncSetAttribute(gemm1_mma, cudaFuncAttributeMaxDynamicSharedMemorySize, G1_SMEM);
    cudaFuncSetAttribute(gemm2_mma, cudaFuncAttributeMaxDynamicSharedMemorySize, G2_SMEM);
    (void)attr_done;

    zero_abar_kernel<<<(BATCH * NPOS + 255) / 256, 256>>>();
    convert_W_kernel<<<(CDIM * CDIM) / 256, 256>>>(Wth, Wph);
    convert_X_kernel<<<dim3((NPOS + 31) / 32, CDIM / 32, BATCH), 256>>>(x_body);

    gemm1_mma<<<dim3(NPOS / 112, CDIM / 128, BATCH), 256, G1_SMEM>>>(bth, bph);
    gemm2_mma<<<dim3(NPOS / 112, NPOS / 112, BATCH), 224, G2_SMEM>>>();

    softmax_stats_kernel<<<dim3(NPOS, BATCH), 256>>>();
    colsum_kernel<<<dim3(NPOS / 112, 8, BATCH), 112>>>();
    xw_kernel<<<dim3(CDIM / 8, BATCH), 256>>>(x_body);
    ybar_kernel<<<dim3(CI / 8, BATCH), 256>>>(Wg, bg);
    pooled_kernel<<<dim3(CDIM / 8, BATCH), 256>>>(Ww, bw, gamma, beta, bmean, bvar);
    h_kernel<<<dim3(CI / 8, BATCH), 256>>>(W1, b1);
    out_kernel<<<BATCH, 256>>>(x_face, W2, b2, out);
}

// round 4
// speedup vs baseline: 3.6475x; 1.4412x over previous
#include <cuda_runtime.h>
#include <cuda_fp16.h>
#include <math_constants.h>
#include <cstdint>

#define BATCH 32
#define CDIM  1024
#define CI    512
#define NPOS  784

// -------- scratch (device globals) --------
__device__ __align__(16) __half g_Wh[(size_t)CDIM * CDIM];                // W hi (theta rows 0..511, phi rows 512..1023)
__device__ __align__(16) __half g_Wl[(size_t)CDIM * CDIM];                // W lo
__device__ __align__(16) __half g_Xt[(size_t)BATCH * NPOS * CDIM];        // X^T fp16 (hi only) [b][n][c]
__device__ __align__(16) __half g_Th[(size_t)BATCH * NPOS * CI];          // theta^T hi [b][n][k]
__device__ __align__(16) __half g_Tl[(size_t)BATCH * NPOS * CI];          // theta^T lo
__device__ __align__(16) __half g_Ph[(size_t)BATCH * NPOS * CI];          // phi^T hi only
__device__ __align__(16) float g_F[(size_t)BATCH * NPOS * NPOS];          // raw logits
__device__ float g_rmax[BATCH * NPOS];
__device__ float g_rscale[BATCH * NPOS];
__device__ float g_abar[BATCH * NPOS];
__device__ float g_xw[BATCH * CDIM];
__device__ float g_xbar[BATCH * CDIM];
__device__ float g_ybar[BATCH * CI];
__device__ float g_pooled[BATCH * CDIM];
__device__ float g_h[BATCH * CI];

// -------- helpers --------
__device__ __forceinline__ uint32_t smem_u32(const void* p) {
    uint32_t a;
    asm("{ .reg .u64 t; cvta.to.shared.u64 t, %1; cvt.u32.u64 %0, t; }" : "=r"(a) : "l"(p));
    return a;
}
__device__ __forceinline__ void cp16(uint32_t dst, const void* src) {
    asm volatile("cp.async.cg.shared.global [%0], [%1], 16;" :: "r"(dst), "l"(src) : "memory");
}
#define CP_COMMIT() asm volatile("cp.async.commit_group;" ::: "memory")
#define CP_WAIT_1() asm volatile("cp.async.wait_group 1;" ::: "memory")

__device__ __forceinline__ void ldsm_x4(uint32_t (&r)[4], uint32_t a) {
    asm volatile("ldmatrix.sync.aligned.m8n8.x4.shared.b16 {%0,%1,%2,%3}, [%4];"
                 : "=r"(r[0]), "=r"(r[1]), "=r"(r[2]), "=r"(r[3]) : "r"(a));
}
__device__ __forceinline__ void ldsm_x2(uint32_t& r0, uint32_t& r1, uint32_t a) {
    asm volatile("ldmatrix.sync.aligned.m8n8.x2.shared.b16 {%0,%1}, [%2];"
                 : "=r"(r0), "=r"(r1) : "r"(a));
}
__device__ __forceinline__ void mma16816(float* c, const uint32_t* a, const uint32_t* b) {
    asm volatile(
        "mma.sync.aligned.m16n8k16.row.col.f32.f16.f16.f32 "
        "{%0,%1,%2,%3}, {%4,%5,%6,%7}, {%8,%9}, {%0,%1,%2,%3};"
        : "+f"(c[0]), "+f"(c[1]), "+f"(c[2]), "+f"(c[3])
        : "r"(a[0]), "r"(a[1]), "r"(a[2]), "r"(a[3]), "r"(b[0]), "r"(b[1]));
}

// ===========================================================================
// conversion: W fp32 -> fp16 hi/lo  (also zeroes g_abar)
// ===========================================================================
__global__ __launch_bounds__(256) void convert_W_kernel(
    const float* __restrict__ Wth, const float* __restrict__ Wph)
{
    int i = blockIdx.x * 256 + threadIdx.x;
    float w = (i < CI * CDIM) ? Wth[i] : Wph[i - CI * CDIM];
    __half hi = __float2half(w);
    g_Wh[i] = hi;
    g_Wl[i] = __float2half(w - __half2float(hi));
    if (i < BATCH * NPOS) g_abar[i] = 0.f;
}

// X transpose + fp16 round (hi only)
__global__ __launch_bounds__(256) void convert_X_kernel(const float* __restrict__ x)
{
    __shared__ float tile[32][33];
    const int b  = blockIdx.z;
    const int c0 = blockIdx.y * 32;
    const int n0 = blockIdx.x * 32;
    const int tx = threadIdx.x & 31;
    const int ty = threadIdx.x >> 5;

    #pragma unroll
    for (int i = 0; i < 4; i++) {
        int c = c0 + ty + i * 8;
        int n = n0 + tx;
        tile[ty + i * 8][tx] = (n < NPOS) ? x[((size_t)b * CDIM + c) * NPOS + n] : 0.f;
    }
    __syncthreads();
    #pragma unroll
    for (int i = 0; i < 4; i++) {
        int n = n0 + ty + i * 8;
        int c = c0 + tx;
        if (n < NPOS)
            g_Xt[((size_t)b * NPOS + n) * CDIM + c] = __float2half(tile[tx][ty + i * 8]);
    }
}

// ===========================================================================
// GEMM1 (warp MMA, fp16 2-product): C[m][n] = sum_k W[m][k] X^T[n][k]
// m tile 128, n tile 112, 8 warps (warp 32x56).
// Epilogue: +bias, transpose; theta rows -> hi/lo, phi rows -> hi only.
// ===========================================================================
#define G1_ASPL  10240           // 128 rows * 80B
#define G1_BOFF  20480
#define G1_STAGE 29440           // A(2 splits) + B(1 split 8960)
#define G1_SMEM  58880

__global__ __launch_bounds__(256, 2) void gemm1_mma(
    const float* __restrict__ bth, const float* __restrict__ bph)
{
    extern __shared__ char smc[];
    const uint32_t sbase = smem_u32(smc);
    const int tid  = threadIdx.x;
    const int lane = tid & 31;
    const int wid  = tid >> 5;
    const int wm   = wid >> 1;           // 0..3  (M)
    const int wn   = wid & 1;            // 0..1  (N)
    const int b    = blockIdx.z;
    const int m0   = blockIdx.y * 128;
    const int n0   = blockIdx.x * 112;

    float acc[14][4];
    #pragma unroll
    for (int i = 0; i < 14; i++)
        #pragma unroll
        for (int j = 0; j < 4; j++) acc[i][j] = 0.f;

    auto issue = [&](int kt, int buf) {
        const int k0 = kt * 32;
        const uint32_t st = sbase + buf * G1_STAGE;
        #pragma unroll
        for (int i = 0; i < 4; i++) {           // A: 1024 tasks (hi+lo)
            int t = tid + i * 256;
            int split = t >> 9, idx = t & 511, row = idx >> 2, ch = idx & 3;
            const __half* src = (split ? g_Wl : g_Wh)
                + (size_t)(m0 + row) * CDIM + k0 + ch * 8;
            cp16(st + split * G1_ASPL + row * 80 + ch * 16, src);
        }
        #pragma unroll
        for (int i = 0; i < 2; i++) {           // B: 448 tasks (hi only)
            int t = tid + i * 256;
            if (t < 448) {
                int row = t >> 2, ch = t & 3;
                const __half* src = g_Xt
                    + ((size_t)b * NPOS + n0 + row) * CDIM + k0 + ch * 8;
                cp16(st + G1_BOFF + row * 80 + ch * 16, src);
            }
        }
        CP_COMMIT();
    };

    issue(0, 0);
    issue(1, 1);

    const int arow = lane & 15;
    const int ach  = lane >> 4;
    const int brow = ((lane >> 4) << 3) + (lane & 7);
    const int bch  = (lane >> 3) & 1;
    const int brow2 = (lane & 15) & 7;
    const int bch2  = ((lane & 15) >> 3) & 1;

    for (int kt = 0; kt < 32; kt++) {
        CP_WAIT_1();
        __syncthreads();
        const uint32_t st = sbase + (kt & 1) * G1_STAGE;
        #pragma unroll
        for (int s = 0; s < 2; s++) {
            uint32_t ah[2][4], al[2][4], bb[7][2];
            #pragma unroll
            for (int i = 0; i < 2; i++) {
                uint32_t aa = st + (wm * 32 + i * 16 + arow) * 80 + (s * 2 + ach) * 16;
                ldsm_x4(ah[i], aa);
                ldsm_x4(al[i], aa + G1_ASPL);
            }
            #pragma unroll
            for (int p = 0; p < 3; p++) {
                uint32_t ba = st + G1_BOFF + (wn * 56 + p * 16 + brow) * 80 + (s * 2 + bch) * 16;
                uint32_t r[4]; ldsm_x4(r, ba);
                bb[p*2][0] = r[0]; bb[p*2][1] = r[1];
                bb[p*2+1][0] = r[2]; bb[p*2+1][1] = r[3];
            }
            ldsm_x2(bb[6][0], bb[6][1],
                    st + G1_BOFF + (wn * 56 + 48 + brow2) * 80 + (s * 2 + bch2) * 16);
            #pragma unroll
            for (int i = 0; i < 2; i++)
                #pragma unroll
                for (int j = 0; j < 7; j++) {
                    mma16816(acc[i*7+j], ah[i], bb[j]);   // Wh * Xh
                    mma16816(acc[i*7+j], al[i], bb[j]);   // Wl * Xh
                }
        }
        __syncthreads();
        if (kt + 2 < 32) issue(kt + 2, kt & 1); else CP_COMMIT();
    }

    // ---- epilogue: smem bounce [ch][n] pitch 113, transposed store
    __syncthreads();
    float* eb = reinterpret_cast<float*>(smc);
    #pragma unroll
    for (int i = 0; i < 2; i++)
        #pragma unroll
        for (int j = 0; j < 7; j++) {
            int row = wm * 32 + i * 16 + (lane >> 2);
            int col = wn * 56 + j * 8 + (lane & 3) * 2;
            eb[row * 113 + col]           = acc[i*7+j][0];
            eb[row * 113 + col + 1]       = acc[i*7+j][1];
            eb[(row + 8) * 113 + col]     = acc[i*7+j][2];
            eb[(row + 8) * 113 + col + 1] = acc[i*7+j][3];
        }
    __syncthreads();

    const bool isTheta = (m0 < CI);
    const int ch0g = isTheta ? m0 : (m0 - CI);
    const float* bias = isTheta ? bth : bph;

    #pragma unroll
    for (int it = 0; it < 7; it++) {
        int t  = tid + it * 256;       // 0..1791
        int cg = t & 15, n = t >> 4;
        int chl = cg * 8;
        __align__(16) __half h8[8], l8[8];
        #pragma unroll
        for (int k = 0; k < 8; k++) {
            float v = eb[(chl + k) * 113 + n] + bias[ch0g + chl + k];
            __half hv = __float2half(v);
            h8[k] = hv;
            l8[k] = __float2half(v - __half2float(hv));
        }
        size_t off = ((size_t)b * NPOS + n0 + n) * CI + ch0g + chl;
        if (isTheta) {
            *reinterpret_cast<uint4*>(g_Th + off) = *reinterpret_cast<const uint4*>(h8);
            *reinterpret_cast<uint4*>(g_Tl + off) = *reinterpret_cast<const uint4*>(l8);
        } else {
            *reinterpret_cast<uint4*>(g_Ph + off) = *reinterpret_cast<const uint4*>(h8);
        }
    }
}

// ===========================================================================
// GEMM2 (warp MMA, fp16 2-product): F[n][m] = sum_k theta^T[n][k] phi^T[m][k]
// tile 112x112xK512, 7 warps (warp = one m16 row-tile, all 112 cols)
// ===========================================================================
#define G2_ASPL  8960
#define G2_BOFF  17920
#define G2_STAGE 26880
#define G2_SMEM  53760

__global__ __launch_bounds__(224, 2) void gemm2_mma()
{
    extern __shared__ char smc[];
    const uint32_t sbase = smem_u32(smc);
    const int tid  = threadIdx.x;
    const int lane = tid & 31;
    const int wid  = tid >> 5;           // 0..6
    const int b    = blockIdx.z;
    const int n0   = blockIdx.y * 112;   // rows (theta)
    const int mb0  = blockIdx.x * 112;   // cols (phi)

    float acc[14][4];
    #pragma unroll
    for (int i = 0; i < 14; i++)
        #pragma unroll
        for (int j = 0; j < 4; j++) acc[i][j] = 0.f;

    auto issue = [&](int kt, int buf) {
        const int k0 = kt * 32;
        const uint32_t st = sbase + buf * G2_STAGE;
        #pragma unroll
        for (int i = 0; i < 4; i++) {    // A: 896 tasks (Th+Tl)
            int t = tid + i * 224;
            int split = (t >= 448);
            int idx = t - split * 448, row = idx >> 2, ch = idx & 3;
            const __half* asrc = (split ? g_Tl : g_Th)
                + ((size_t)b * NPOS + n0 + row) * CI + k0 + ch * 8;
            cp16(st + split * G2_ASPL + row * 80 + ch * 16, asrc);
        }
        #pragma unroll
        for (int i = 0; i < 2; i++) {    // B: 448 tasks (Ph only)
            int t = tid + i * 224;
            if (t < 448) {
                int row = t >> 2, ch = t & 3;
                const __half* bsrc = g_Ph
                    + ((size_t)b * NPOS + mb0 + row) * CI + k0 + ch * 8;
                cp16(st + G2_BOFF + row * 80 + ch * 16, bsrc);
            }
        }
        CP_COMMIT();
    };

    issue(0, 0);
    issue(1, 1);

    const int arow = lane & 15;
    const int ach  = lane >> 4;
    const int brow = ((lane >> 4) << 3) + (lane & 7);
    const int bch  = (lane >> 3) & 1;

    for (int kt = 0; kt < 16; kt++) {
        CP_WAIT_1();
        __syncthreads();
        const uint32_t st = sbase + (kt & 1) * G2_STAGE;
        #pragma unroll
        for (int s = 0; s < 2; s++) {
            uint32_t ah[4], al[4], bb[14][2];
            uint32_t aa = st + (wid * 16 + arow) * 80 + (s * 2 + ach) * 16;
            ldsm_x4(ah, aa);
            ldsm_x4(al, aa + G2_ASPL);
            #pragma unroll
            for (int p = 0; p < 7; p++) {
                uint32_t ba = st + G2_BOFF + (p * 16 + brow) * 80 + (s * 2 + bch) * 16;
                uint32_t r[4]; ldsm_x4(r, ba);
                bb[p*2][0] = r[0]; bb[p*2][1] = r[1];
                bb[p*2+1][0] = r[2]; bb[p*2+1][1] = r[3];
            }
            #pragma unroll
            for (int j = 0; j < 14; j++) {
                mma16816(acc[j], ah, bb[j]);
                mma16816(acc[j], al, bb[j]);
            }
        }
        __syncthreads();
        if (kt + 2 < 16) issue(kt + 2, kt & 1); else CP_COMMIT();
    }

    // epilogue: smem bounce [112][116], coalesced float4 stores
    __syncthreads();
    float* eb = reinterpret_cast<float*>(smc);
    #pragma unroll
    for (int j = 0; j < 14; j++) {
        int row = wid * 16 + (lane >> 2);
        int col = j * 8 + (lane & 3) * 2;
        eb[row * 116 + col]           = acc[j][0];
        eb[row * 116 + col + 1]       = acc[j][1];
        eb[(row + 8) * 116 + col]     = acc[j][2];
        eb[(row + 8) * 116 + col + 1] = acc[j][3];
    }
    __syncthreads();
    #pragma unroll
    for (int i = 0; i < 14; i++) {
        int t = tid + i * 224;          // 0..3135
        int row = t / 28, c4 = t % 28;
        float4 v = *reinterpret_cast<const float4*>(&eb[row * 116 + c4 * 4]);
        *reinterpret_cast<float4*>(g_F + ((size_t)b * NPOS + n0 + row) * NPOS + mb0 + c4 * 4) = v;
    }
}

// ===========================================================================
// softmax stats: warp per row, values register-resident (single DRAM pass)
// ===========================================================================
__global__ __launch_bounds__(256) void softmax_stats_kernel()
{
    const int r    = blockIdx.x * 8 + (threadIdx.x >> 5);   // global row id
    const int lane = threadIdx.x & 31;
    const float4* __restrict__ row4 =
        reinterpret_cast<const float4*>(g_F + (size_t)r * NPOS);

    float4 v[7];
    #pragma unroll
    for (int k = 0; k < 7; k++) {
        int c4 = lane + k * 32;
        if (k < 6 || c4 < 196) v[k] = row4[c4];
        else v[k] = make_float4(-CUDART_INF_F, -CUDART_INF_F, -CUDART_INF_F, -CUDART_INF_F);
    }
    float m = -CUDART_INF_F;
    #pragma unroll
    for (int k = 0; k < 7; k++)
        m = fmaxf(m, fmaxf(fmaxf(v[k].x, v[k].y), fmaxf(v[k].z, v[k].w)));
    #pragma unroll
    for (int o = 16; o; o >>= 1) m = fmaxf(m, __shfl_xor_sync(0xffffffffu, m, o));

    float s = 0.f;
    #pragma unroll
    for (int k = 0; k < 7; k++) {
        s += __expf(v[k].x - m) + __expf(v[k].y - m)
           + __expf(v[k].z - m) + __expf(v[k].w - m);   // exp(-inf)=0 for pad
    }
    #pragma unroll
    for (int o = 16; o; o >>= 1) s += __shfl_xor_sync(0xffffffffu, s, o);

    if (lane == 0) {
        g_rmax[r]   = m;
        g_rscale[r] = 1.f / (s * (float)NPOS);
    }
}

// a_bar[b][m] = sum_n exp(F[n][m]-rmax[n]) * rscale[n]
__global__ __launch_bounds__(112) void colsum_kernel()
{
    const int b  = blockIdx.z;
    const int m  = blockIdx.x * 112 + threadIdx.x;
    const int n0 = blockIdx.y * 112;

    __shared__ float srs[112];
    __shared__ float smx[112];
    srs[threadIdx.x] = g_rscale[b * NPOS + n0 + threadIdx.x];
    smx[threadIdx.x] = g_rmax[b * NPOS + n0 + threadIdx.x];
    __syncthreads();

    const float* __restrict__ Fb = g_F + ((size_t)b * NPOS + n0) * NPOS + m;
    float acc = 0.f;
    #pragma unroll 8
    for (int j = 0; j < 112; j++)
        acc += __expf(Fb[(size_t)j * NPOS] - smx[j]) * srs[j];
    atomicAdd(&g_abar[b * NPOS + m], acc);
}

__global__ __launch_bounds__(256) void xw_kernel(const float* __restrict__ x)
{
    const int b    = blockIdx.y;
    const int c    = blockIdx.x * 8 + (threadIdx.x >> 5);
    const int lane = threadIdx.x & 31;

    __shared__ float sa[NPOS];
    for (int i = threadIdx.x; i < NPOS; i += 256) sa[i] = g_abar[b * NPOS + i];
    __syncthreads();

    const float* __restrict__ xr = x + ((size_t)b * CDIM + c) * NPOS;
    float dot = 0.f, sum = 0.f;
    for (int i = lane; i < NPOS; i += 32) {
        float v = xr[i];
        dot = fmaf(v, sa[i], dot);
        sum += v;
    }
    #pragma unroll
    for (int o = 16; o; o >>= 1) {
        dot += __shfl_xor_sync(0xffffffffu, dot, o);
        sum += __shfl_xor_sync(0xffffffffu, sum, o);
    }
    if (lane == 0) {
        g_xw[b * CDIM + c]   = dot;
        g_xbar[b * CDIM + c] = sum * (1.f / (float)NPOS);
    }
}

__global__ __launch_bounds__(256) void ybar_kernel(const float* __restrict__ Wg,
                                                   const float* __restrict__ bg)
{
    const int b    = blockIdx.y;
    const int i    = blockIdx.x * 8 + (threadIdx.x >> 5);
    const int lane = threadIdx.x & 31;

    __shared__ float sx[CDIM];
    for (int k = threadIdx.x; k < CDIM; k += 256) sx[k] = g_xw[b * CDIM + k];
    __syncthreads();

    const float* __restrict__ w = Wg + (size_t)i * CDIM;
    float d = 0.f;
    for (int k = lane; k < CDIM; k += 32) d = fmaf(w[k], sx[k], d);
    #pragma unroll
    for (int o = 16; o; o >>= 1) d += __shfl_xor_sync(0xffffffffu, d, o);
    if (lane == 0) g_ybar[b * CI + i] = d + bg[i];
}

__global__ __launch_bounds__(256) void pooled_kernel(
    const float* __restrict__ Ww, const float* __restrict__ bw,
    const float* __restrict__ gamma, const float* __restrict__ beta,
    const float* __restrict__ bmean, const float* __restrict__ bvar)
{
    const int b    = blockIdx.y;
    const int c    = blockIdx.x * 8 + (threadIdx.x >> 5);
    const int lane = threadIdx.x & 31;

    __shared__ float sy[CI];
    for (int k = threadIdx.x; k < CI; k += 256) sy[k] = g_ybar[b * CI + k];
    __syncthreads();

    const float* __restrict__ w = Ww + (size_t)c * CI;
    float d = 0.f;
    for (int k = lane; k < CI; k += 32) d = fmaf(w[k], sy[k], d);
    #pragma unroll
    for (int o = 16; o; o >>= 1) d += __shfl_xor_sync(0xffffffffu, d, o);
    if (lane == 0) {
        float inv = gamma[c] * rsqrtf(bvar[c] + 1e-5f);
        g_pooled[b * CDIM + c] =
            inv * (d + bw[c]) + (beta[c] - bmean[c] * inv) + g_xbar[b * CDIM + c];
    }
}

__global__ __launch_bounds__(256) void h_kernel(const float* __restrict__ W1,
                                                const float* __restrict__ b1)
{
    const int b    = blockIdx.y;
    const int j    = blockIdx.x * 8 + (threadIdx.x >> 5);
    const int lane = threadIdx.x & 31;

    __shared__ float sp[CDIM];
    for (int k = threadIdx.x; k < CDIM; k += 256) sp[k] = g_pooled[b * CDIM + k];
    __syncthreads();

    const float* __restrict__ w = W1 + (size_t)j * CDIM;
    float d = 0.f;
    for (int k = lane; k < CDIM; k += 32) d = fmaf(w[k], sp[k], d);
    #pragma unroll
    for (int o = 16; o; o >>= 1) d += __shfl_xor_sync(0xffffffffu, d, o);
    if (lane == 0) g_h[b * CI + j] = d + b1[j];
}

__global__ __launch_bounds__(256) void out_kernel(const float* __restrict__ xface,
                                                  const float* __restrict__ W2,
                                                  const float* __restrict__ b2,
                                                  float* __restrict__ out)
{
    const int b = blockIdx.x;
    const int o = threadIdx.x >> 7;
    const int t = threadIdx.x & 127;

    float acc = 0.f;
    for (int k = t; k < CDIM; k += 128) {
        float v = (k < CI) ? g_h[b * CI + k] : xface[b * CI + (k - CI)];
        acc = fmaf(W2[o * CDIM + k], v, acc);
    }
    #pragma unroll
    for (int off = 16; off; off >>= 1) acc += __shfl_xor_sync(0xffffffffu, acc, off);

    __shared__ float sred[8];
    const int warp = threadIdx.x >> 5;
    if ((threadIdx.x & 31) == 0) sred[warp] = acc;
    __syncthreads();
    if (threadIdx.x == 0)
        out[b * 2 + 0] = sred[0] + sred[1] + sred[2] + sred[3] + b2[0];
    if (threadIdx.x == 128)
        out[b * 2 + 1] = sred[4] + sred[5] + sred[6] + sred[7] + b2[1];
}

// ===========================================================================
extern "C" void kernel_launch(void* const* d_in, const int* in_sizes, int n_in,
                              void* d_out, int out_size)
{
    const float* x_body = (const float*)d_in[0];
    const float* x_face = (const float*)d_in[1];
    const float* Wg     = (const float*)d_in[2];
    const float* bg     = (const float*)d_in[3];
    const float* Wth    = (const float*)d_in[4];
    const float* bth    = (const float*)d_in[5];
    const float* Wph    = (const float*)d_in[6];
    const float* bph    = (const float*)d_in[7];
    const float* Ww     = (const float*)d_in[8];
    const float* bw     = (const float*)d_in[9];
    const float* gamma  = (const float*)d_in[10];
    const float* beta   = (const float*)d_in[11];
    const float* bmean  = (const float*)d_in[12];
    const float* bvar   = (const float*)d_in[13];
    const float* W1     = (const float*)d_in[14];
    const float* b1     = (const float*)d_in[15];
    const float* W2     = (const float*)d_in[16];
    const float* b2     = (const float*)d_in[17];
    float* out = (float*)d_out;

    cudaFuncSetAttribute(gemm1_mma, cudaFuncAttributeMaxDynamicSharedMemorySize, G1_SMEM);
    cudaFuncSetAttribute(gemm2_mma, cudaFuncAttributeMaxDynamicSharedMemorySize, G2_SMEM);

    convert_W_kernel<<<(CDIM * CDIM) / 256, 256>>>(Wth, Wph);
    convert_X_kernel<<<dim3((NPOS + 31) / 32, CDIM / 32, BATCH), 256>>>(x_body);

    gemm1_mma<<<dim3(NPOS / 112, CDIM / 128, BATCH), 256, G1_SMEM>>>(bth, bph);
    gemm2_mma<<<dim3(NPOS / 112, NPOS / 112, BATCH), 224, G2_SMEM>>>();

    softmax_stats_kernel<<<BATCH * NPOS / 8, 256>>>();
    colsum_kernel<<<dim3(NPOS / 112, NPOS / 112, BATCH), 112>>>();
    xw_kernel<<<dim3(CDIM / 8, BATCH), 256>>>(x_body);
    ybar_kernel<<<dim3(CI / 8, BATCH), 256>>>(Wg, bg);
    pooled_kernel<<<dim3(CDIM / 8, BATCH), 256>>>(Ww, bw, gamma, beta, bmean, bvar);
    h_kernel<<<dim3(CI / 8, BATCH), 256>>>(W1, b1);
    out_kernel<<<BATCH, 256>>>(x_face, W2, b2, out);
}

// round 6
// speedup vs baseline: 4.9186x; 1.3485x over previous
#include <cuda_runtime.h>
#include <cuda_fp16.h>
#include <math_constants.h>
#include <cstdint>

#define BATCH 32
#define CDIM  1024
#define CI    512
#define NPOS  784

// -------- scratch (device globals) --------
__device__ __align__(16) __half g_Wh[(size_t)CDIM * CDIM];          // W fp16 (theta rows 0..511, phi 512..1023)
__device__ __align__(16) __half g_Xt[(size_t)BATCH * NPOS * CDIM];  // X^T fp16 [b][n][c]
__device__ __align__(16) __half g_Th[(size_t)BATCH * NPOS * CI];    // theta^T fp16 [b][n][k]
__device__ __align__(16) __half g_Ph[(size_t)BATCH * NPOS * CI];    // phi^T fp16
__device__ __align__(16) float g_F[(size_t)BATCH * NPOS * NPOS];    // raw logits
__device__ float g_rmax[BATCH * NPOS];
__device__ float g_rscale[BATCH * NPOS];
__device__ float g_abar[BATCH * NPOS];
__device__ float g_xw[BATCH * CDIM];
__device__ float g_xbar[BATCH * CDIM];
__device__ float g_ybar[BATCH * CI];
__device__ float g_pooled[BATCH * CDIM];
__device__ float g_h[BATCH * CI];

// -------- helpers --------
__device__ __forceinline__ uint32_t smem_u32(const void* p) {
    uint32_t a;
    asm("{ .reg .u64 t; cvta.to.shared.u64 t, %1; cvt.u32.u64 %0, t; }" : "=r"(a) : "l"(p));
    return a;
}
__device__ __forceinline__ void cp16(uint32_t dst, const void* src) {
    asm volatile("cp.async.cg.shared.global [%0], [%1], 16;" :: "r"(dst), "l"(src) : "memory");
}
#define CP_COMMIT() asm volatile("cp.async.commit_group;" ::: "memory")
#define CP_WAIT_1() asm volatile("cp.async.wait_group 1;" ::: "memory")

__device__ __forceinline__ void ldsm_x4(uint32_t (&r)[4], uint32_t a) {
    asm volatile("ldmatrix.sync.aligned.m8n8.x4.shared.b16 {%0,%1,%2,%3}, [%4];"
                 : "=r"(r[0]), "=r"(r[1]), "=r"(r[2]), "=r"(r[3]) : "r"(a));
}
__device__ __forceinline__ void ldsm_x2(uint32_t& r0, uint32_t& r1, uint32_t a) {
    asm volatile("ldmatrix.sync.aligned.m8n8.x2.shared.b16 {%0,%1}, [%2];"
                 : "=r"(r0), "=r"(r1) : "r"(a));
}
__device__ __forceinline__ void mma16816(float* c, const uint32_t* a, const uint32_t* b) {
    asm volatile(
        "mma.sync.aligned.m16n8k16.row.col.f32.f16.f16.f32 "
        "{%0,%1,%2,%3}, {%4,%5,%6,%7}, {%8,%9}, {%0,%1,%2,%3};"
        : "+f"(c[0]), "+f"(c[1]), "+f"(c[2]), "+f"(c[3])
        : "r"(a[0]), "r"(a[1]), "r"(a[2]), "r"(a[3]), "r"(b[0]), "r"(b[1]));
}

// ===========================================================================
// conversions
// ===========================================================================
__global__ __launch_bounds__(256) void convert_W_kernel(
    const float* __restrict__ Wth, const float* __restrict__ Wph)
{
    int i = blockIdx.x * 256 + threadIdx.x;
    float w = (i < CI * CDIM) ? Wth[i] : Wph[i - CI * CDIM];
    g_Wh[i] = __float2half(w);
    if (i < BATCH * NPOS) g_abar[i] = 0.f;
}

__global__ __launch_bounds__(256) void convert_X_kernel(const float* __restrict__ x)
{
    __shared__ float tile[32][33];
    const int b  = blockIdx.z;
    const int c0 = blockIdx.y * 32;
    const int n0 = blockIdx.x * 32;
    const int tx = threadIdx.x & 31;
    const int ty = threadIdx.x >> 5;

    #pragma unroll
    for (int i = 0; i < 4; i++) {
        int c = c0 + ty + i * 8;
        int n = n0 + tx;
        tile[ty + i * 8][tx] = (n < NPOS) ? x[((size_t)b * CDIM + c) * NPOS + n] : 0.f;
    }
    __syncthreads();
    #pragma unroll
    for (int i = 0; i < 4; i++) {
        int n = n0 + ty + i * 8;
        int c = c0 + tx;
        if (n < NPOS)
            g_Xt[((size_t)b * NPOS + n) * CDIM + c] = __float2half(tile[tx][ty + i * 8]);
    }
}

// ===========================================================================
// GEMM1 (warp MMA, single fp16 product): C[m][n] = sum_k W[m][k] X^T[n][k]
// m tile 128, n tile 112, 8 warps (warp 32x56).
// SMEM: max(2*19200 pipeline, 57856 fp32 epilogue bounce) = 57856
// ===========================================================================
#define G1_BOFF  10240           // A: 128 rows * 80B
#define G1_STAGE 19200           // + B: 112 rows * 80B
#define G1_SMEM  57856

__global__ __launch_bounds__(256, 2) void gemm1_mma(
    const float* __restrict__ bth, const float* __restrict__ bph)
{
    extern __shared__ char smc[];
    const uint32_t sbase = smem_u32(smc);
    const int tid  = threadIdx.x;
    const int lane = tid & 31;
    const int wid  = tid >> 5;
    const int wm   = wid >> 1;           // 0..3  (M)
    const int wn   = wid & 1;            // 0..1  (N)
    const int b    = blockIdx.z;
    const int m0   = blockIdx.y * 128;
    const int n0   = blockIdx.x * 112;

    float acc[14][4];
    #pragma unroll
    for (int i = 0; i < 14; i++)
        #pragma unroll
        for (int j = 0; j < 4; j++) acc[i][j] = 0.f;

    auto issue = [&](int kt, int buf) {
        const int k0 = kt * 32;
        const uint32_t st = sbase + buf * G1_STAGE;
        #pragma unroll
        for (int i = 0; i < 2; i++) {           // A: 512 tasks
            int t = tid + i * 256;
            int row = t >> 2, ch = t & 3;
            const __half* src = g_Wh + (size_t)(m0 + row) * CDIM + k0 + ch * 8;
            cp16(st + row * 80 + ch * 16, src);
        }
        #pragma unroll
        for (int i = 0; i < 2; i++) {           // B: 448 tasks
            int t = tid + i * 256;
            if (t < 448) {
                int row = t >> 2, ch = t & 3;
                const __half* src = g_Xt
                    + ((size_t)b * NPOS + n0 + row) * CDIM + k0 + ch * 8;
                cp16(st + G1_BOFF + row * 80 + ch * 16, src);
            }
        }
        CP_COMMIT();
    };

    issue(0, 0);
    issue(1, 1);

    const int arow = lane & 15;
    const int ach  = lane >> 4;
    const int brow = ((lane >> 4) << 3) + (lane & 7);
    const int bch  = (lane >> 3) & 1;
    const int brow2 = (lane & 15) & 7;
    const int bch2  = ((lane & 15) >> 3) & 1;

    for (int kt = 0; kt < 32; kt++) {
        CP_WAIT_1();
        __syncthreads();
        const uint32_t st = sbase + (kt & 1) * G1_STAGE;
        #pragma unroll
        for (int s = 0; s < 2; s++) {
            uint32_t ah[2][4], bb[7][2];
            #pragma unroll
            for (int i = 0; i < 2; i++) {
                uint32_t aa = st + (wm * 32 + i * 16 + arow) * 80 + (s * 2 + ach) * 16;
                ldsm_x4(ah[i], aa);
            }
            #pragma unroll
            for (int p = 0; p < 3; p++) {
                uint32_t ba = st + G1_BOFF + (wn * 56 + p * 16 + brow) * 80 + (s * 2 + bch) * 16;
                uint32_t r[4]; ldsm_x4(r, ba);
                bb[p*2][0] = r[0]; bb[p*2][1] = r[1];
                bb[p*2+1][0] = r[2]; bb[p*2+1][1] = r[3];
            }
            ldsm_x2(bb[6][0], bb[6][1],
                    st + G1_BOFF + (wn * 56 + 48 + brow2) * 80 + (s * 2 + bch2) * 16);
            #pragma unroll
            for (int i = 0; i < 2; i++)
                #pragma unroll
                for (int j = 0; j < 7; j++)
                    mma16816(acc[i*7+j], ah[i], bb[j]);
        }
        __syncthreads();
        if (kt + 2 < 32) issue(kt + 2, kt & 1); else CP_COMMIT();
    }

    // ---- epilogue: smem bounce [ch][n] pitch 113 (fp32, 57856B), transposed fp16 store
    __syncthreads();
    float* eb = reinterpret_cast<float*>(smc);
    #pragma unroll
    for (int i = 0; i < 2; i++)
        #pragma unroll
        for (int j = 0; j < 7; j++) {
            int row = wm * 32 + i * 16 + (lane >> 2);
            int col = wn * 56 + j * 8 + (lane & 3) * 2;
            eb[row * 113 + col]           = acc[i*7+j][0];
            eb[row * 113 + col + 1]       = acc[i*7+j][1];
            eb[(row + 8) * 113 + col]     = acc[i*7+j][2];
            eb[(row + 8) * 113 + col + 1] = acc[i*7+j][3];
        }
    __syncthreads();

    const bool isTheta = (m0 < CI);
    __half* dst = isTheta ? g_Th : g_Ph;
    const int ch0g = isTheta ? m0 : (m0 - CI);
    const float* bias = isTheta ? bth : bph;

    #pragma unroll
    for (int it = 0; it < 7; it++) {
        int t  = tid + it * 256;       // 0..1791
        int cg = t & 15, n = t >> 4;
        int chl = cg * 8;
        __align__(16) __half h8[8];
        #pragma unroll
        for (int k = 0; k < 8; k++)
            h8[k] = __float2half(eb[(chl + k) * 113 + n] + bias[ch0g + chl + k]);
        size_t off = ((size_t)b * NPOS + n0 + n) * CI + ch0g + chl;
        *reinterpret_cast<uint4*>(dst + off) = *reinterpret_cast<const uint4*>(h8);
    }
}

// ===========================================================================
// GEMM2 (warp MMA, single fp16 product): F[n][m] = sum_k Th[n][k] Ph[m][k]
// tile 112x112xK512, 7 warps.
// SMEM: max(2*17920 pipeline, 51968 fp32 epilogue bounce) = 51968
// ===========================================================================
#define G2_BOFF  8960
#define G2_STAGE 17920
#define G2_SMEM  51968

__global__ __launch_bounds__(224, 2) void gemm2_mma()
{
    extern __shared__ char smc[];
    const uint32_t sbase = smem_u32(smc);
    const int tid  = threadIdx.x;
    const int lane = tid & 31;
    const int wid  = tid >> 5;           // 0..6
    const int b    = blockIdx.z;
    const int n0   = blockIdx.y * 112;   // rows (theta)
    const int mb0  = blockIdx.x * 112;   // cols (phi)

    float acc[14][4];
    #pragma unroll
    for (int i = 0; i < 14; i++)
        #pragma unroll
        for (int j = 0; j < 4; j++) acc[i][j] = 0.f;

    auto issue = [&](int kt, int buf) {
        const int k0 = kt * 32;
        const uint32_t st = sbase + buf * G2_STAGE;
        #pragma unroll
        for (int i = 0; i < 2; i++) {    // A: 448 tasks
            int t = tid + i * 224;
            int row = t >> 2, ch = t & 3;
            const __half* asrc = g_Th
                + ((size_t)b * NPOS + n0 + row) * CI + k0 + ch * 8;
            cp16(st + row * 80 + ch * 16, asrc);
        }
        #pragma unroll
        for (int i = 0; i < 2; i++) {    // B: 448 tasks
            int t = tid + i * 224;
            int row = t >> 2, ch = t & 3;
            const __half* bsrc = g_Ph
                + ((size_t)b * NPOS + mb0 + row) * CI + k0 + ch * 8;
            cp16(st + G2_BOFF + row * 80 + ch * 16, bsrc);
        }
        CP_COMMIT();
    };

    issue(0, 0);
    issue(1, 1);

    const int arow = lane & 15;
    const int ach  = lane >> 4;
    const int brow = ((lane >> 4) << 3) + (lane & 7);
    const int bch  = (lane >> 3) & 1;

    for (int kt = 0; kt < 16; kt++) {
        CP_WAIT_1();
        __syncthreads();
        const uint32_t st = sbase + (kt & 1) * G2_STAGE;
        #pragma unroll
        for (int s = 0; s < 2; s++) {
            uint32_t ah[4], bb[14][2];
            uint32_t aa = st + (wid * 16 + arow) * 80 + (s * 2 + ach) * 16;
            ldsm_x4(ah, aa);
            #pragma unroll
            for (int p = 0; p < 7; p++) {
                uint32_t ba = st + G2_BOFF + (p * 16 + brow) * 80 + (s * 2 + bch) * 16;
                uint32_t r[4]; ldsm_x4(r, ba);
                bb[p*2][0] = r[0]; bb[p*2][1] = r[1];
                bb[p*2+1][0] = r[2]; bb[p*2+1][1] = r[3];
            }
            #pragma unroll
            for (int j = 0; j < 14; j++)
                mma16816(acc[j], ah, bb[j]);
        }
        __syncthreads();
        if (kt + 2 < 16) issue(kt + 2, kt & 1); else CP_COMMIT();
    }

    // epilogue: smem bounce [112][116] fp32 (51968B), coalesced float4 stores
    __syncthreads();
    float* eb = reinterpret_cast<float*>(smc);
    #pragma unroll
    for (int j = 0; j < 14; j++) {
        int row = wid * 16 + (lane >> 2);
        int col = j * 8 + (lane & 3) * 2;
        eb[row * 116 + col]           = acc[j][0];
        eb[row * 116 + col + 1]       = acc[j][1];
        eb[(row + 8) * 116 + col]     = acc[j][2];
        eb[(row + 8) * 116 + col + 1] = acc[j][3];
    }
    __syncthreads();
    #pragma unroll
    for (int i = 0; i < 14; i++) {
        int t = tid + i * 224;          // 0..3135
        int row = t / 28, c4 = t % 28;
        float4 v = *reinterpret_cast<const float4*>(&eb[row * 116 + c4 * 4]);
        *reinterpret_cast<float4*>(g_F + ((size_t)b * NPOS + n0 + row) * NPOS + mb0 + c4 * 4) = v;
    }
}

// ===========================================================================
// softmax stats: warp per row, register-resident single DRAM pass
// ===========================================================================
__global__ __launch_bounds__(256) void softmax_stats_kernel()
{
    const int r    = blockIdx.x * 8 + (threadIdx.x >> 5);
    const int lane = threadIdx.x & 31;
    const float4* __restrict__ row4 =
        reinterpret_cast<const float4*>(g_F + (size_t)r * NPOS);

    float4 v[7];
    #pragma unroll
    for (int k = 0; k < 7; k++) {
        int c4 = lane + k * 32;
        if (k < 6 || c4 < 196) v[k] = row4[c4];
        else v[k] = make_float4(-CUDART_INF_F, -CUDART_INF_F, -CUDART_INF_F, -CUDART_INF_F);
    }
    float m = -CUDART_INF_F;
    #pragma unroll
    for (int k = 0; k < 7; k++)
        m = fmaxf(m, fmaxf(fmaxf(v[k].x, v[k].y), fmaxf(v[k].z, v[k].w)));
    #pragma unroll
    for (int o = 16; o; o >>= 1) m = fmaxf(m, __shfl_xor_sync(0xffffffffu, m, o));

    float s = 0.f;
    #pragma unroll
    for (int k = 0; k < 7; k++) {
        s += __expf(v[k].x - m) + __expf(v[k].y - m)
           + __expf(v[k].z - m) + __expf(v[k].w - m);
    }
    #pragma unroll
    for (int o = 16; o; o >>= 1) s += __shfl_xor_sync(0xffffffffu, s, o);

    if (lane == 0) {
        g_rmax[r]   = m;
        g_rscale[r] = 1.f / (s * (float)NPOS);
    }
}

// a_bar[b][m] = sum_n exp(F[n][m]-rmax[n]) * rscale[n]
__global__ __launch_bounds__(112) void colsum_kernel()
{
    const int b  = blockIdx.z;
    const int m  = blockIdx.x * 112 + threadIdx.x;
    const int n0 = blockIdx.y * 112;

    __shared__ float srs[112];
    __shared__ float smx[112];
    srs[threadIdx.x] = g_rscale[b * NPOS + n0 + threadIdx.x];
    smx[threadIdx.x] = g_rmax[b * NPOS + n0 + threadIdx.x];
    __syncthreads();

    const float* __restrict__ Fb = g_F + ((size_t)b * NPOS + n0) * NPOS + m;
    float acc = 0.f;
    #pragma unroll 8
    for (int j = 0; j < 112; j++)
        acc += __expf(Fb[(size_t)j * NPOS] - smx[j]) * srs[j];
    atomicAdd(&g_abar[b * NPOS + m], acc);
}

__global__ __launch_bounds__(256) void xw_kernel(const float* __restrict__ x)
{
    const int b    = blockIdx.y;
    const int c    = blockIdx.x * 8 + (threadIdx.x >> 5);
    const int lane = threadIdx.x & 31;

    __shared__ float sa[NPOS];
    for (int i = threadIdx.x; i < NPOS; i += 256) sa[i] = g_abar[b * NPOS + i];
    __syncthreads();

    const float* __restrict__ xr = x + ((size_t)b * CDIM + c) * NPOS;
    float dot = 0.f, sum = 0.f;
    for (int i = lane; i < NPOS; i += 32) {
        float v = xr[i];
        dot = fmaf(v, sa[i], dot);
        sum += v;
    }
    #pragma unroll
    for (int o = 16; o; o >>= 1) {
        dot += __shfl_xor_sync(0xffffffffu, dot, o);
        sum += __shfl_xor_sync(0xffffffffu, sum, o);
    }
    if (lane == 0) {
        g_xw[b * CDIM + c]   = dot;
        g_xbar[b * CDIM + c] = sum * (1.f / (float)NPOS);
    }
}

__global__ __launch_bounds__(256) void ybar_kernel(const float* __restrict__ Wg,
                                                   const float* __restrict__ bg)
{
    const int b    = blockIdx.y;
    const int i    = blockIdx.x * 8 + (threadIdx.x >> 5);
    const int lane = threadIdx.x & 31;

    __shared__ float sx[CDIM];
    for (int k = threadIdx.x; k < CDIM; k += 256) sx[k] = g_xw[b * CDIM + k];
    __syncthreads();

    const float* __restrict__ w = Wg + (size_t)i * CDIM;
    float d = 0.f;
    for (int k = lane; k < CDIM; k += 32) d = fmaf(w[k], sx[k], d);
    #pragma unroll
    for (int o = 16; o; o >>= 1) d += __shfl_xor_sync(0xffffffffu, d, o);
    if (lane == 0) g_ybar[b * CI + i] = d + bg[i];
}

__global__ __launch_bounds__(256) void pooled_kernel(
    const float* __restrict__ Ww, const float* __restrict__ bw,
    const float* __restrict__ gamma, const float* __restrict__ beta,
    const float* __restrict__ bmean, const float* __restrict__ bvar)
{
    const int b    = blockIdx.y;
    const int c    = blockIdx.x * 8 + (threadIdx.x >> 5);
    const int lane = threadIdx.x & 31;

    __shared__ float sy[CI];
    for (int k = threadIdx.x; k < CI; k += 256) sy[k] = g_ybar[b * CI + k];
    __syncthreads();

    const float* __restrict__ w = Ww + (size_t)c * CI;
    float d = 0.f;
    for (int k = lane; k < CI; k += 32) d = fmaf(w[k], sy[k], d);
    #pragma unroll
    for (int o = 16; o; o >>= 1) d += __shfl_xor_sync(0xffffffffu, d, o);
    if (lane == 0) {
        float inv = gamma[c] * rsqrtf(bvar[c] + 1e-5f);
        g_pooled[b * CDIM + c] =
            inv * (d + bw[c]) + (beta[c] - bmean[c] * inv) + g_xbar[b * CDIM + c];
    }
}

__global__ __launch_bounds__(256) void h_kernel(const float* __restrict__ W1,
                                                const float* __restrict__ b1)
{
    const int b    = blockIdx.y;
    const int j    = blockIdx.x * 8 + (threadIdx.x >> 5);
    const int lane = threadIdx.x & 31;

    __shared__ float sp[CDIM];
    for (int k = threadIdx.x; k < CDIM; k += 256) sp[k] = g_pooled[b * CDIM + k];
    __syncthreads();

    const float* __restrict__ w = W1 + (size_t)j * CDIM;
    float d = 0.f;
    for (int k = lane; k < CDIM; k += 32) d = fmaf(w[k], sp[k], d);
    #pragma unroll
    for (int o = 16; o; o >>= 1) d += __shfl_xor_sync(0xffffffffu, d, o);
    if (lane == 0) g_h[b * CI + j] = d + b1[j];
}

__global__ __launch_bounds__(256) void out_kernel(const float* __restrict__ xface,
                                                  const float* __restrict__ W2,
                                                  const float* __restrict__ b2,
                                                  float* __restrict__ out)
{
    const int b = blockIdx.x;
    const int o = threadIdx.x >> 7;
    const int t = threadIdx.x & 127;

    float acc = 0.f;
    for (int k = t; k < CDIM; k += 128) {
        float v = (k < CI) ? g_h[b * CI + k] : xface[b * CI + (k - CI)];
        acc = fmaf(W2[o * CDIM + k], v, acc);
    }
    #pragma unroll
    for (int off = 16; off; off >>= 1) acc += __shfl_xor_sync(0xffffffffu, acc, off);

    __shared__ float sred[8];
    const int warp = threadIdx.x >> 5;
    if ((threadIdx.x & 31) == 0) sred[warp] = acc;
    __syncthreads();
    if (threadIdx.x == 0)
        out[b * 2 + 0] = sred[0] + sred[1] + sred[2] + sred[3] + b2[0];
    if (threadIdx.x == 128)
        out[b * 2 + 1] = sred[4] + sred[5] + sred[6] + sred[7] + b2[1];
}

// ===========================================================================
extern "C" void kernel_launch(void* const* d_in, const int* in_sizes, int n_in,
                              void* d_out, int out_size)
{
    const float* x_body = (const float*)d_in[0];
    const float* x_face = (const float*)d_in[1];
    const float* Wg     = (const float*)d_in[2];
    const float* bg     = (const float*)d_in[3];
    const float* Wth    = (const float*)d_in[4];
    const float* bth    = (const float*)d_in[5];
    const float* Wph    = (const float*)d_in[6];
    const float* bph    = (const float*)d_in[7];
    const float* Ww     = (const float*)d_in[8];
    const float* bw     = (const float*)d_in[9];
    const float* gamma  = (const float*)d_in[10];
    const float* beta   = (const float*)d_in[11];
    const float* bmean  = (const float*)d_in[12];
    const float* bvar   = (const float*)d_in[13];
    const float* W1     = (const float*)d_in[14];
    const float* b1     = (const float*)d_in[15];
    const float* W2     = (const float*)d_in[16];
    const float* b2     = (const float*)d_in[17];
    float* out = (float*)d_out;

    cudaFuncSetAttribute(gemm1_mma, cudaFuncAttributeMaxDynamicSharedMemorySize, G1_SMEM);
    cudaFuncSetAttribute(gemm2_mma, cudaFuncAttributeMaxDynamicSharedMemorySize, G2_SMEM);

    convert_W_kernel<<<(CDIM * CDIM) / 256, 256>>>(Wth, Wph);
    convert_X_kernel<<<dim3((NPOS + 31) / 32, CDIM / 32, BATCH), 256>>>(x_body);

    gemm1_mma<<<dim3(NPOS / 112, CDIM / 128, BATCH), 256, G1_SMEM>>>(bth, bph);
    gemm2_mma<<<dim3(NPOS / 112, NPOS / 112, BATCH), 224, G2_SMEM>>>();

    softmax_stats_kernel<<<BATCH * NPOS / 8, 256>>>();
    colsum_kernel<<<dim3(NPOS / 112, NPOS / 112, BATCH), 112>>>();
    xw_kernel<<<dim3(CDIM / 8, BATCH), 256>>>(x_body);
    ybar_kernel<<<dim3(CI / 8, BATCH), 256>>>(Wg, bg);
    pooled_kernel<<<dim3(CDIM / 8, BATCH), 256>>>(Ww, bw, gamma, beta, bmean, bvar);
    h_kernel<<<dim3(CI / 8, BATCH), 256>>>(W1, b1);
    out_kernel<<<BATCH, 256>>>(x_face, W2, b2, out);
}

// round 7
// speedup vs baseline: 5.0518x; 1.0271x over previous
#include <cuda_runtime.h>
#include <cuda_fp16.h>
#include <math_constants.h>
#include <cstdint>

#define BATCH 32
#define CDIM  1024
#define CI    512
#define NPOS  784

// -------- scratch (device globals) --------
__device__ __align__(16) __half g_Wh[(size_t)CDIM * CDIM];          // W fp16 (theta rows 0..511, phi 512..1023)
__device__ __align__(16) __half g_Xt[(size_t)BATCH * NPOS * CDIM];  // X^T fp16 [b][n][c]
__device__ __align__(16) __half g_Th[(size_t)BATCH * NPOS * CI];    // theta^T fp16 [b][n][k]
__device__ __align__(16) __half g_Ph[(size_t)BATCH * NPOS * CI];    // phi^T fp16
__device__ __align__(16) float g_F[(size_t)BATCH * NPOS * NPOS];    // raw logits
__device__ float g_rmax[BATCH * NPOS];
__device__ float g_rscale[BATCH * NPOS];
__device__ float g_abar[BATCH * NPOS];
__device__ float g_xw[BATCH * CDIM];
__device__ float g_xbar[BATCH * CDIM];
__device__ float g_ybar[BATCH * CI];
__device__ float g_pooled[BATCH * CDIM];
__device__ float g_h[BATCH * CI];

// -------- helpers --------
__device__ __forceinline__ uint32_t smem_u32(const void* p) {
    uint32_t a;
    asm("{ .reg .u64 t; cvta.to.shared.u64 t, %1; cvt.u32.u64 %0, t; }" : "=r"(a) : "l"(p));
    return a;
}
__device__ __forceinline__ void cp16(uint32_t dst, const void* src) {
    asm volatile("cp.async.cg.shared.global [%0], [%1], 16;" :: "r"(dst), "l"(src) : "memory");
}
#define CP_COMMIT() asm volatile("cp.async.commit_group;" ::: "memory")
#define CP_WAIT_1() asm volatile("cp.async.wait_group 1;" ::: "memory")

__device__ __forceinline__ void ldsm_x4(uint32_t (&r)[4], uint32_t a) {
    asm volatile("ldmatrix.sync.aligned.m8n8.x4.shared.b16 {%0,%1,%2,%3}, [%4];"
                 : "=r"(r[0]), "=r"(r[1]), "=r"(r[2]), "=r"(r[3]) : "r"(a));
}
__device__ __forceinline__ void ldsm_x2(uint32_t& r0, uint32_t& r1, uint32_t a) {
    asm volatile("ldmatrix.sync.aligned.m8n8.x2.shared.b16 {%0,%1}, [%2];"
                 : "=r"(r0), "=r"(r1) : "r"(a));
}
__device__ __forceinline__ void mma16816(float* c, const uint32_t* a, const uint32_t* b) {
    asm volatile(
        "mma.sync.aligned.m16n8k16.row.col.f32.f16.f16.f32 "
        "{%0,%1,%2,%3}, {%4,%5,%6,%7}, {%8,%9}, {%0,%1,%2,%3};"
        : "+f"(c[0]), "+f"(c[1]), "+f"(c[2]), "+f"(c[3])
        : "r"(a[0]), "r"(a[1]), "r"(a[2]), "r"(a[3]), "r"(b[0]), "r"(b[1]));
}

// ===========================================================================
// conversions
// ===========================================================================
__global__ __launch_bounds__(256) void convert_W_kernel(
    const float* __restrict__ Wth, const float* __restrict__ Wph)
{
    int i = blockIdx.x * 256 + threadIdx.x;
    float w = (i < CI * CDIM) ? Wth[i] : Wph[i - CI * CDIM];
    g_Wh[i] = __float2half(w);
    if (i < BATCH * NPOS) g_abar[i] = 0.f;
}

__global__ __launch_bounds__(256) void convert_X_kernel(const float* __restrict__ x)
{
    __shared__ float tile[32][33];
    const int b  = blockIdx.z;
    const int c0 = blockIdx.y * 32;
    const int n0 = blockIdx.x * 32;
    const int tx = threadIdx.x & 31;
    const int ty = threadIdx.x >> 5;

    #pragma unroll
    for (int i = 0; i < 4; i++) {
        int c = c0 + ty + i * 8;
        int n = n0 + tx;
        tile[ty + i * 8][tx] = (n < NPOS) ? x[((size_t)b * CDIM + c) * NPOS + n] : 0.f;
    }
    __syncthreads();
    #pragma unroll
    for (int i = 0; i < 4; i++) {
        int n = n0 + ty + i * 8;
        int c = c0 + tx;
        if (n < NPOS)
            g_Xt[((size_t)b * NPOS + n) * CDIM + c] = __float2half(tile[tx][ty + i * 8]);
    }
}

// ===========================================================================
// GEMM1 (warp MMA, fp16): C[m][n] = sum_k W[m][k] X^T[n][k]
// CTA tile 128x112, 4 warps (2M x 2N), warp tile 64x56.
// SMEM: max(2*19200 pipeline, 57856 fp32 epilogue bounce) = 57856
// ===========================================================================
#define G1_BOFF  10240           // A: 128 rows * 80B
#define G1_STAGE 19200           // + B: 112 rows * 80B
#define G1_SMEM  57856

__global__ __launch_bounds__(128, 2) void gemm1_mma(
    const float* __restrict__ bth, const float* __restrict__ bph)
{
    extern __shared__ char smc[];
    const uint32_t sbase = smem_u32(smc);
    const int tid  = threadIdx.x;
    const int lane = tid & 31;
    const int wid  = tid >> 5;           // 0..3
    const int wm   = wid >> 1;           // 0..1  (M, 64 rows)
    const int wn   = wid & 1;            // 0..1  (N, 56 cols)
    const int b    = blockIdx.z;
    const int m0   = blockIdx.y * 128;
    const int n0   = blockIdx.x * 112;

    float acc[28][4];                    // [i*7+j], i<4 (16-row frag), j<7 (8-col frag)
    #pragma unroll
    for (int i = 0; i < 28; i++)
        #pragma unroll
        for (int j = 0; j < 4; j++) acc[i][j] = 0.f;

    auto issue = [&](int kt, int buf) {
        const int k0 = kt * 32;
        const uint32_t st = sbase + buf * G1_STAGE;
        #pragma unroll
        for (int i = 0; i < 4; i++) {           // A: 512 tasks
            int t = tid + i * 128;
            int row = t >> 2, ch = t & 3;
            const __half* src = g_Wh + (size_t)(m0 + row) * CDIM + k0 + ch * 8;
            cp16(st + row * 80 + ch * 16, src);
        }
        #pragma unroll
        for (int i = 0; i < 4; i++) {           // B: 448 tasks
            int t = tid + i * 128;
            if (t < 448) {
                int row = t >> 2, ch = t & 3;
                const __half* src = g_Xt
                    + ((size_t)b * NPOS + n0 + row) * CDIM + k0 + ch * 8;
                cp16(st + G1_BOFF + row * 80 + ch * 16, src);
            }
        }
        CP_COMMIT();
    };

    issue(0, 0);
    issue(1, 1);

    const int arow = lane & 15;
    const int ach  = lane >> 4;
    const int brow = ((lane >> 4) << 3) + (lane & 7);
    const int bch  = (lane >> 3) & 1;
    const int brow2 = (lane & 15) & 7;
    const int bch2  = ((lane & 15) >> 3) & 1;

    for (int kt = 0; kt < 32; kt++) {
        CP_WAIT_1();
        __syncthreads();
        const uint32_t st = sbase + (kt & 1) * G1_STAGE;
        #pragma unroll
        for (int s = 0; s < 2; s++) {
            uint32_t ah[4][4], bb[7][2];
            #pragma unroll
            for (int p = 0; p < 3; p++) {
                uint32_t ba = st + G1_BOFF + (wn * 56 + p * 16 + brow) * 80 + (s * 2 + bch) * 16;
                uint32_t r[4]; ldsm_x4(r, ba);
                bb[p*2][0] = r[0]; bb[p*2][1] = r[1];
                bb[p*2+1][0] = r[2]; bb[p*2+1][1] = r[3];
            }
            ldsm_x2(bb[6][0], bb[6][1],
                    st + G1_BOFF + (wn * 56 + 48 + brow2) * 80 + (s * 2 + bch2) * 16);
            #pragma unroll
            for (int i = 0; i < 4; i++) {
                uint32_t aa = st + (wm * 64 + i * 16 + arow) * 80 + (s * 2 + ach) * 16;
                ldsm_x4(ah[i], aa);
            }
            #pragma unroll
            for (int i = 0; i < 4; i++)
                #pragma unroll
                for (int j = 0; j < 7; j++)
                    mma16816(acc[i*7+j], ah[i], bb[j]);
        }
        __syncthreads();
        if (kt + 2 < 32) issue(kt + 2, kt & 1); else CP_COMMIT();
    }

    // ---- epilogue: smem bounce [ch][n] pitch 113 (fp32, 57856B), transposed fp16 store
    __syncthreads();
    float* eb = reinterpret_cast<float*>(smc);
    #pragma unroll
    for (int i = 0; i < 4; i++)
        #pragma unroll
        for (int j = 0; j < 7; j++) {
            int row = wm * 64 + i * 16 + (lane >> 2);
            int col = wn * 56 + j * 8 + (lane & 3) * 2;
            eb[row * 113 + col]           = acc[i*7+j][0];
            eb[row * 113 + col + 1]       = acc[i*7+j][1];
            eb[(row + 8) * 113 + col]     = acc[i*7+j][2];
            eb[(row + 8) * 113 + col + 1] = acc[i*7+j][3];
        }
    __syncthreads();

    const bool isTheta = (m0 < CI);
    __half* dst = isTheta ? g_Th : g_Ph;
    const int ch0g = isTheta ? m0 : (m0 - CI);
    const float* bias = isTheta ? bth : bph;

    #pragma unroll
    for (int it = 0; it < 14; it++) {
        int t  = tid + it * 128;       // 0..1791
        int cg = t & 15, n = t >> 4;
        int chl = cg * 8;
        __align__(16) __half h8[8];
        #pragma unroll
        for (int k = 0; k < 8; k++)
            h8[k] = __float2half(eb[(chl + k) * 113 + n] + bias[ch0g + chl + k]);
        size_t off = ((size_t)b * NPOS + n0 + n) * CI + ch0g + chl;
        *reinterpret_cast<uint4*>(dst + off) = *reinterpret_cast<const uint4*>(h8);
    }
}

// ===========================================================================
// GEMM2 (warp MMA, fp16): F[n][m] = sum_k Th[n][k] Ph[m][k]
// tile 112x112xK512, 7 warps; register-lean B loads for 3 CTAs/SM.
// SMEM: max(2*17920 pipeline, 51968 fp32 epilogue bounce) = 51968
// ===========================================================================
#define G2_BOFF  8960
#define G2_STAGE 17920
#define G2_SMEM  51968

__global__ __launch_bounds__(224, 3) void gemm2_mma()
{
    extern __shared__ char smc[];
    const uint32_t sbase = smem_u32(smc);
    const int tid  = threadIdx.x;
    const int lane = tid & 31;
    const int wid  = tid >> 5;           // 0..6
    const int b    = blockIdx.z;
    const int n0   = blockIdx.y * 112;   // rows (theta)
    const int mb0  = blockIdx.x * 112;   // cols (phi)

    float acc[14][4];
    #pragma unroll
    for (int i = 0; i < 14; i++)
        #pragma unroll
        for (int j = 0; j < 4; j++) acc[i][j] = 0.f;

    auto issue = [&](int kt, int buf) {
        const int k0 = kt * 32;
        const uint32_t st = sbase + buf * G2_STAGE;
        #pragma unroll
        for (int i = 0; i < 2; i++) {    // A: 448 tasks
            int t = tid + i * 224;
            int row = t >> 2, ch = t & 3;
            const __half* asrc = g_Th
                + ((size_t)b * NPOS + n0 + row) * CI + k0 + ch * 8;
            cp16(st + row * 80 + ch * 16, asrc);
        }
        #pragma unroll
        for (int i = 0; i < 2; i++) {    // B: 448 tasks
            int t = tid + i * 224;
            int row = t >> 2, ch = t & 3;
            const __half* bsrc = g_Ph
                + ((size_t)b * NPOS + mb0 + row) * CI + k0 + ch * 8;
            cp16(st + G2_BOFF + row * 80 + ch * 16, bsrc);
        }
        CP_COMMIT();
    };

    issue(0, 0);
    issue(1, 1);

    const int arow = lane & 15;
    const int ach  = lane >> 4;
    const int brow = ((lane >> 4) << 3) + (lane & 7);
    const int bch  = (lane >> 3) & 1;

    for (int kt = 0; kt < 16; kt++) {
        CP_WAIT_1();
        __syncthreads();
        const uint32_t st = sbase + (kt & 1) * G2_STAGE;
        #pragma unroll
        for (int s = 0; s < 2; s++) {
            uint32_t ah[4];
            uint32_t aa = st + (wid * 16 + arow) * 80 + (s * 2 + ach) * 16;
            ldsm_x4(ah, aa);
            #pragma unroll
            for (int p = 0; p < 7; p++) {
                uint32_t ba = st + G2_BOFF + (p * 16 + brow) * 80 + (s * 2 + bch) * 16;
                uint32_t r[4]; ldsm_x4(r, ba);
                mma16816(acc[p*2],     ah, &r[0]);
                mma16816(acc[p*2 + 1], ah, &r[2]);
            }
        }
        __syncthreads();
        if (kt + 2 < 16) issue(kt + 2, kt & 1); else CP_COMMIT();
    }

    // epilogue: smem bounce [112][116] fp32 (51968B), coalesced float4 stores
    __syncthreads();
    float* eb = reinterpret_cast<float*>(smc);
    #pragma unroll
    for (int j = 0; j < 14; j++) {
        int row = wid * 16 + (lane >> 2);
        int col = j * 8 + (lane & 3) * 2;
        eb[row * 116 + col]           = acc[j][0];
        eb[row * 116 + col + 1]       = acc[j][1];
        eb[(row + 8) * 116 + col]     = acc[j][2];
        eb[(row + 8) * 116 + col + 1] = acc[j][3];
    }
    __syncthreads();
    #pragma unroll
    for (int i = 0; i < 14; i++) {
        int t = tid + i * 224;          // 0..3135
        int row = t / 28, c4 = t % 28;
        float4 v = *reinterpret_cast<const float4*>(&eb[row * 116 + c4 * 4]);
        *reinterpret_cast<float4*>(g_F + ((size_t)b * NPOS + n0 + row) * NPOS + mb0 + c4 * 4) = v;
    }
}

// ===========================================================================
// softmax stats: warp per row, register-resident single DRAM pass
// ===========================================================================
__global__ __launch_bounds__(256) void softmax_stats_kernel()
{
    const int r    = blockIdx.x * 8 + (threadIdx.x >> 5);
    const int lane = threadIdx.x & 31;
    const float4* __restrict__ row4 =
        reinterpret_cast<const float4*>(g_F + (size_t)r * NPOS);

    float4 v[7];
    #pragma unroll
    for (int k = 0; k < 7; k++) {
        int c4 = lane + k * 32;
        if (k < 6 || c4 < 196) v[k] = row4[c4];
        else v[k] = make_float4(-CUDART_INF_F, -CUDART_INF_F, -CUDART_INF_F, -CUDART_INF_F);
    }
    float m = -CUDART_INF_F;
    #pragma unroll
    for (int k = 0; k < 7; k++)
        m = fmaxf(m, fmaxf(fmaxf(v[k].x, v[k].y), fmaxf(v[k].z, v[k].w)));
    #pragma unroll
    for (int o = 16; o; o >>= 1) m = fmaxf(m, __shfl_xor_sync(0xffffffffu, m, o));

    float s = 0.f;
    #pragma unroll
    for (int k = 0; k < 7; k++) {
        s += __expf(v[k].x - m) + __expf(v[k].y - m)
           + __expf(v[k].z - m) + __expf(v[k].w - m);
    }
    #pragma unroll
    for (int o = 16; o; o >>= 1) s += __shfl_xor_sync(0xffffffffu, s, o);

    if (lane == 0) {
        g_rmax[r]   = m;
        g_rscale[r] = 1.f / (s * (float)NPOS);
    }
}

// a_bar[b][m] = sum_n exp(F[n][m]-rmax[n]) * rscale[n]
__global__ __launch_bounds__(112) void colsum_kernel()
{
    const int b  = blockIdx.z;
    const int m  = blockIdx.x * 112 + threadIdx.x;
    const int n0 = blockIdx.y * 112;

    __shared__ float srs[112];
    __shared__ float smx[112];
    srs[threadIdx.x] = g_rscale[b * NPOS + n0 + threadIdx.x];
    smx[threadIdx.x] = g_rmax[b * NPOS + n0 + threadIdx.x];
    __syncthreads();

    const float* __restrict__ Fb = g_F + ((size_t)b * NPOS + n0) * NPOS + m;
    float acc = 0.f;
    #pragma unroll 8
    for (int j = 0; j < 112; j++)
        acc += __expf(Fb[(size_t)j * NPOS] - smx[j]) * srs[j];
    atomicAdd(&g_abar[b * NPOS + m], acc);
}

__global__ __launch_bounds__(256) void xw_kernel(const float* __restrict__ x)
{
    const int b    = blockIdx.y;
    const int c    = blockIdx.x * 8 + (threadIdx.x >> 5);
    const int lane = threadIdx.x & 31;

    __shared__ float sa[NPOS];
    for (int i = threadIdx.x; i < NPOS; i += 256) sa[i] = g_abar[b * NPOS + i];
    __syncthreads();

    const float* __restrict__ xr = x + ((size_t)b * CDIM + c) * NPOS;
    float dot = 0.f, sum = 0.f;
    for (int i = lane; i < NPOS; i += 32) {
        float v = xr[i];
        dot = fmaf(v, sa[i], dot);
        sum += v;
    }
    #pragma unroll
    for (int o = 16; o; o >>= 1) {
        dot += __shfl_xor_sync(0xffffffffu, dot, o);
        sum += __shfl_xor_sync(0xffffffffu, sum, o);
    }
    if (lane == 0) {
        g_xw[b * CDIM + c]   = dot;
        g_xbar[b * CDIM + c] = sum * (1.f / (float)NPOS);
    }
}

__global__ __launch_bounds__(256) void ybar_kernel(const float* __restrict__ Wg,
                                                   const float* __restrict__ bg)
{
    const int b    = blockIdx.y;
    const int i    = blockIdx.x * 8 + (threadIdx.x >> 5);
    const int lane = threadIdx.x & 31;

    __shared__ float sx[CDIM];
    for (int k = threadIdx.x; k < CDIM; k += 256) sx[k] = g_xw[b * CDIM + k];
    __syncthreads();

    const float* __restrict__ w = Wg + (size_t)i * CDIM;
    float d = 0.f;
    for (int k = lane; k < CDIM; k += 32) d = fmaf(w[k], sx[k], d);
    #pragma unroll
    for (int o = 16; o; o >>= 1) d += __shfl_xor_sync(0xffffffffu, d, o);
    if (lane == 0) g_ybar[b * CI + i] = d + bg[i];
}

__global__ __launch_bounds__(256) void pooled_kernel(
    const float* __restrict__ Ww, const float* __restrict__ bw,
    const float* __restrict__ gamma, const float* __restrict__ beta,
    const float* __restrict__ bmean, const float* __restrict__ bvar)
{
    const int b    = blockIdx.y;
    const int c    = blockIdx.x * 8 + (threadIdx.x >> 5);
    const int lane = threadIdx.x & 31;

    __shared__ float sy[CI];
    for (int k = threadIdx.x; k < CI; k += 256) sy[k] = g_ybar[b * CI + k];
    __syncthreads();

    const float* __restrict__ w = Ww + (size_t)c * CI;
    float d = 0.f;
    for (int k = lane; k < CI; k += 32) d = fmaf(w[k], sy[k], d);
    #pragma unroll
    for (int o = 16; o; o >>= 1) d += __shfl_xor_sync(0xffffffffu, d, o);
    if (lane == 0) {
        float inv = gamma[c] * rsqrtf(bvar[c] + 1e-5f);
        g_pooled[b * CDIM + c] =
            inv * (d + bw[c]) + (beta[c] - bmean[c] * inv) + g_xbar[b * CDIM + c];
    }
}

__global__ __launch_bounds__(256) void h_kernel(const float* __restrict__ W1,
                                                const float* __restrict__ b1)
{
    const int b    = blockIdx.y;
    const int j    = blockIdx.x * 8 + (threadIdx.x >> 5);
    const int lane = threadIdx.x & 31;

    __shared__ float sp[CDIM];
    for (int k = threadIdx.x; k < CDIM; k += 256) sp[k] = g_pooled[b * CDIM + k];
    __syncthreads();

    const float* __restrict__ w = W1 + (size_t)j * CDIM;
    float d = 0.f;
    for (int k = lane; k < CDIM; k += 32) d = fmaf(w[k], sp[k], d);
    #pragma unroll
    for (int o = 16; o; o >>= 1) d += __shfl_xor_sync(0xffffffffu, d, o);
    if (lane == 0) g_h[b * CI + j] = d + b1[j];
}

__global__ __launch_bounds__(256) void out_kernel(const float* __restrict__ xface,
                                                  const float* __restrict__ W2,
                                                  const float* __restrict__ b2,
                                                  float* __restrict__ out)
{
    const int b = blockIdx.x;
    const int o = threadIdx.x >> 7;
    const int t = threadIdx.x & 127;

    float acc = 0.f;
    for (int k = t; k < CDIM; k += 128) {
        float v = (k < CI) ? g_h[b * CI + k] : xface[b * CI + (k - CI)];
        acc = fmaf(W2[o * CDIM + k], v, acc);
    }
    #pragma unroll
    for (int off = 16; off; off >>= 1) acc += __shfl_xor_sync(0xffffffffu, acc, off);

    __shared__ float sred[8];
    const int warp = threadIdx.x >> 5;
    if ((threadIdx.x & 31) == 0) sred[warp] = acc;
    __syncthreads();
    if (threadIdx.x == 0)
        out[b * 2 + 0] = sred[0] + sred[1] + sred[2] + sred[3] + b2[0];
    if (threadIdx.x == 128)
        out[b * 2 + 1] = sred[4] + sred[5] + sred[6] + sred[7] + b2[1];
}

// ===========================================================================
extern "C" void kernel_launch(void* const* d_in, const int* in_sizes, int n_in,
                              void* d_out, int out_size)
{
    const float* x_body = (const float*)d_in[0];
    const float* x_face = (const float*)d_in[1];
    const float* Wg     = (const float*)d_in[2];
    const float* bg     = (const float*)d_in[3];
    const float* Wth    = (const float*)d_in[4];
    const float* bth    = (const float*)d_in[5];
    const float* Wph    = (const float*)d_in[6];
    const float* bph    = (const float*)d_in[7];
    const float* Ww     = (const float*)d_in[8];
    const float* bw     = (const float*)d_in[9];
    const float* gamma  = (const float*)d_in[10];
    const float* beta   = (const float*)d_in[11];
    const float* bmean  = (const float*)d_in[12];
    const float* bvar   = (const float*)d_in[13];
    const float* W1     = (const float*)d_in[14];
    const float* b1     = (const float*)d_in[15];
    const float* W2     = (const float*)d_in[16];
    const float* b2     = (const float*)d_in[17];
    float* out = (float*)d_out;

    cudaFuncSetAttribute(gemm1_mma, cudaFuncAttributeMaxDynamicSharedMemorySize, G1_SMEM);
    cudaFuncSetAttribute(gemm2_mma, cudaFuncAttributeMaxDynamicSharedMemorySize, G2_SMEM);

    convert_W_kernel<<<(CDIM * CDIM) / 256, 256>>>(Wth, Wph);
    convert_X_kernel<<<dim3((NPOS + 31) / 32, CDIM / 32, BATCH), 256>>>(x_body);

    gemm1_mma<<<dim3(NPOS / 112, CDIM / 128, BATCH), 128, G1_SMEM>>>(bth, bph);
    gemm2_mma<<<dim3(NPOS / 112, NPOS / 112, BATCH), 224, G2_SMEM>>>();

    softmax_stats_kernel<<<BATCH * NPOS / 8, 256>>>();
    colsum_kernel<<<dim3(NPOS / 112, NPOS / 112, BATCH), 112>>>();
    xw_kernel<<<dim3(CDIM / 8, BATCH), 256>>>(x_body);
    ybar_kernel<<<dim3(CI / 8, BATCH), 256>>>(Wg, bg);
    pooled_kernel<<<dim3(CDIM / 8, BATCH), 256>>>(Ww, bw, gamma, beta, bmean, bvar);
    h_kernel<<<dim3(CI / 8, BATCH), 256>>>(W1, b1);
    out_kernel<<<BATCH, 256>>>(x_face, W2, b2, out);
}

// round 8
// speedup vs baseline: 5.2365x; 1.0366x over previous
#include <cuda_runtime.h>
#include <cuda_fp16.h>
#include <math_constants.h>
#include <cstdint>

#define BATCH 32
#define CDIM  1024
#define CI    512
#define NPOS  784

// -------- scratch (device globals) --------
__device__ __align__(16) __half g_Wh[(size_t)CDIM * CDIM];          // W fp16 (theta rows 0..511, phi 512..1023)
__device__ __align__(16) __half g_Xt[(size_t)BATCH * NPOS * CDIM];  // X^T fp16 [b][n][c]
__device__ __align__(16) __half g_Th[(size_t)BATCH * NPOS * CI];    // theta^T fp16 [b][n][k]
__device__ __align__(16) __half g_Ph[(size_t)BATCH * NPOS * CI];    // phi^T fp16
__device__ __align__(16) float g_F[(size_t)BATCH * NPOS * NPOS];    // raw logits
__device__ float g_rmax[BATCH * NPOS];
__device__ float g_rscale[BATCH * NPOS];
__device__ float g_abar[BATCH * NPOS];
__device__ float g_xw[BATCH * CDIM];
__device__ float g_xbar[BATCH * CDIM];
__device__ float g_ybar[BATCH * CI];
__device__ float g_pooled[BATCH * CDIM];
__device__ float g_h[BATCH * CI];

// -------- helpers --------
__device__ __forceinline__ uint32_t smem_u32(const void* p) {
    uint32_t a;
    asm("{ .reg .u64 t; cvta.to.shared.u64 t, %1; cvt.u32.u64 %0, t; }" : "=r"(a) : "l"(p));
    return a;
}
__device__ __forceinline__ void cp16(uint32_t dst, const void* src) {
    asm volatile("cp.async.cg.shared.global [%0], [%1], 16;" :: "r"(dst), "l"(src) : "memory");
}
#define CP_COMMIT() asm volatile("cp.async.commit_group;" ::: "memory")
#define CP_WAIT_1() asm volatile("cp.async.wait_group 1;" ::: "memory")

__device__ __forceinline__ void ldsm_x4(uint32_t (&r)[4], uint32_t a) {
    asm volatile("ldmatrix.sync.aligned.m8n8.x4.shared.b16 {%0,%1,%2,%3}, [%4];"
                 : "=r"(r[0]), "=r"(r[1]), "=r"(r[2]), "=r"(r[3]) : "r"(a));
}
__device__ __forceinline__ void ldsm_x2(uint32_t& r0, uint32_t& r1, uint32_t a) {
    asm volatile("ldmatrix.sync.aligned.m8n8.x2.shared.b16 {%0,%1}, [%2];"
                 : "=r"(r0), "=r"(r1) : "r"(a));
}
__device__ __forceinline__ void mma16816(float* c, const uint32_t* a, const uint32_t* b) {
    asm volatile(
        "mma.sync.aligned.m16n8k16.row.col.f32.f16.f16.f32 "
        "{%0,%1,%2,%3}, {%4,%5,%6,%7}, {%8,%9}, {%0,%1,%2,%3};"
        : "+f"(c[0]), "+f"(c[1]), "+f"(c[2]), "+f"(c[3])
        : "r"(a[0]), "r"(a[1]), "r"(a[2]), "r"(a[3]), "r"(b[0]), "r"(b[1]));
}

// ===========================================================================
// conversions
// ===========================================================================
__global__ __launch_bounds__(256) void convert_W_kernel(
    const float* __restrict__ Wth, const float* __restrict__ Wph)
{
    int i = blockIdx.x * 256 + threadIdx.x;
    float w = (i < CI * CDIM) ? Wth[i] : Wph[i - CI * CDIM];
    g_Wh[i] = __float2half(w);
    if (i < BATCH * NPOS) g_abar[i] = 0.f;
}

__global__ __launch_bounds__(256) void convert_X_kernel(const float* __restrict__ x)
{
    __shared__ float tile[32][33];
    const int b  = blockIdx.z;
    const int c0 = blockIdx.y * 32;
    const int n0 = blockIdx.x * 32;
    const int tx = threadIdx.x & 31;
    const int ty = threadIdx.x >> 5;

    #pragma unroll
    for (int i = 0; i < 4; i++) {
        int c = c0 + ty + i * 8;
        int n = n0 + tx;
        tile[ty + i * 8][tx] = (n < NPOS) ? x[((size_t)b * CDIM + c) * NPOS + n] : 0.f;
    }
    __syncthreads();
    #pragma unroll
    for (int i = 0; i < 4; i++) {
        int n = n0 + ty + i * 8;
        int c = c0 + tx;
        if (n < NPOS)
            g_Xt[((size_t)b * NPOS + n) * CDIM + c] = __float2half(tile[tx][ty + i * 8]);
    }
}

// ===========================================================================
// GEMM1 (warp MMA, fp16): C[m][n] = sum_k W[m][k] X^T[n][k]
// CTA tile 128x112, 4 warps (2M x 2N), warp tile 64x56.
// Epilogue: fp16 bounce in [n][ch] layout (pitch 144) -> uint4 stores.
// SMEM: max(2*19200 pipeline, 112*144*2=32256 bounce) = 38400 -> 3 CTA/SM
// ===========================================================================
#define G1_BOFF  10240           // A: 128 rows * 80B
#define G1_STAGE 19200           // + B: 112 rows * 80B
#define G1_SMEM  38400
#define G1_EPITCH 144            // halves per n-row in epilogue bounce

__global__ __launch_bounds__(128, 3) void gemm1_mma(
    const float* __restrict__ bth, const float* __restrict__ bph)
{
    extern __shared__ char smc[];
    const uint32_t sbase = smem_u32(smc);
    const int tid  = threadIdx.x;
    const int lane = tid & 31;
    const int wid  = tid >> 5;           // 0..3
    const int wm   = wid >> 1;           // 0..1  (M, 64 rows)
    const int wn   = wid & 1;            // 0..1  (N, 56 cols)
    const int b    = blockIdx.z;
    const int m0   = blockIdx.y * 128;
    const int n0   = blockIdx.x * 112;

    float acc[28][4];                    // [i*7+j], i<4 (16-row frag), j<7 (8-col frag)
    #pragma unroll
    for (int i = 0; i < 28; i++)
        #pragma unroll
        for (int j = 0; j < 4; j++) acc[i][j] = 0.f;

    auto issue = [&](int kt, int buf) {
        const int k0 = kt * 32;
        const uint32_t st = sbase + buf * G1_STAGE;
        #pragma unroll
        for (int i = 0; i < 4; i++) {           // A: 512 tasks
            int t = tid + i * 128;
            int row = t >> 2, ch = t & 3;
            const __half* src = g_Wh + (size_t)(m0 + row) * CDIM + k0 + ch * 8;
            cp16(st + row * 80 + ch * 16, src);
        }
        #pragma unroll
        for (int i = 0; i < 4; i++) {           // B: 448 tasks
            int t = tid + i * 128;
            if (t < 448) {
                int row = t >> 2, ch = t & 3;
                const __half* src = g_Xt
                    + ((size_t)b * NPOS + n0 + row) * CDIM + k0 + ch * 8;
                cp16(st + G1_BOFF + row * 80 + ch * 16, src);
            }
        }
        CP_COMMIT();
    };

    issue(0, 0);
    issue(1, 1);

    const int arow = lane & 15;
    const int ach  = lane >> 4;
    const int brow = ((lane >> 4) << 3) + (lane & 7);
    const int bch  = (lane >> 3) & 1;
    const int brow2 = (lane & 15) & 7;
    const int bch2  = ((lane & 15) >> 3) & 1;

    for (int kt = 0; kt < 32; kt++) {
        CP_WAIT_1();
        __syncthreads();
        const uint32_t st = sbase + (kt & 1) * G1_STAGE;
        #pragma unroll
        for (int s = 0; s < 2; s++) {
            uint32_t ah[4][4], bb[7][2];
            #pragma unroll
            for (int p = 0; p < 3; p++) {
                uint32_t ba = st + G1_BOFF + (wn * 56 + p * 16 + brow) * 80 + (s * 2 + bch) * 16;
                uint32_t r[4]; ldsm_x4(r, ba);
                bb[p*2][0] = r[0]; bb[p*2][1] = r[1];
                bb[p*2+1][0] = r[2]; bb[p*2+1][1] = r[3];
            }
            ldsm_x2(bb[6][0], bb[6][1],
                    st + G1_BOFF + (wn * 56 + 48 + brow2) * 80 + (s * 2 + bch2) * 16);
            #pragma unroll
            for (int i = 0; i < 4; i++) {
                uint32_t aa = st + (wm * 64 + i * 16 + arow) * 80 + (s * 2 + ach) * 16;
                ldsm_x4(ah[i], aa);
            }
            #pragma unroll
            for (int i = 0; i < 4; i++)
                #pragma unroll
                for (int j = 0; j < 7; j++)
                    mma16816(acc[i*7+j], ah[i], bb[j]);
        }
        __syncthreads();
        if (kt + 2 < 32) issue(kt + 2, kt & 1); else CP_COMMIT();
    }

    // ---- epilogue: fp16 bounce [n][ch] pitch 144, then uint4 biased stores
    __syncthreads();
    __half* eb = reinterpret_cast<__half*>(smc);
    #pragma unroll
    for (int i = 0; i < 4; i++)
        #pragma unroll
        for (int j = 0; j < 7; j++) {
            int ch  = wm * 64 + i * 16 + (lane >> 2);
            int col = wn * 56 + j * 8 + (lane & 3) * 2;
            eb[col * G1_EPITCH + ch]           = __float2half(acc[i*7+j][0]);
            eb[(col + 1) * G1_EPITCH + ch]     = __float2half(acc[i*7+j][1]);
            eb[col * G1_EPITCH + ch + 8]       = __float2half(acc[i*7+j][2]);
            eb[(col + 1) * G1_EPITCH + ch + 8] = __float2half(acc[i*7+j][3]);
        }
    __syncthreads();

    const bool isTheta = (m0 < CI);
    __half* dst = isTheta ? g_Th : g_Ph;
    const int ch0g = isTheta ? m0 : (m0 - CI);
    const float* bias = isTheta ? bth : bph;

    #pragma unroll
    for (int it = 0; it < 14; it++) {
        int t  = tid + it * 128;       // 0..1791
        int cg = t & 15, n = t >> 4;
        int chl = cg * 8;
        uint4 raw = *reinterpret_cast<const uint4*>(eb + n * G1_EPITCH + chl);
        const __half* rh = reinterpret_cast<const __half*>(&raw);
        __align__(16) __half h8[8];
        #pragma unroll
        for (int k = 0; k < 8; k++)
            h8[k] = __float2half(__half2float(rh[k]) + bias[ch0g + chl + k]);
        size_t off = ((size_t)b * NPOS + n0 + n) * CI + ch0g + chl;
        *reinterpret_cast<uint4*>(dst + off) = *reinterpret_cast<const uint4*>(h8);
    }
}

// ===========================================================================
// GEMM2 (warp MMA, fp16): F[n][m] = sum_k Th[n][k] Ph[m][k]
// CTA tile 128(n, clamped at 784) x 112(m), 8 warps (4M x 2N), warp 32x56.
// SMEM: max(2*19200 pipeline, 128*116*4=59392 fp32 epilogue) = 59392
// ===========================================================================
#define G2_BOFF  10240           // A: 128 rows * 80B
#define G2_STAGE 19200           // + B: 112 rows * 80B
#define G2_SMEM  59392
#define G2_EPITCH 116

__global__ __launch_bounds__(256, 2) void gemm2_mma()
{
    extern __shared__ char smc[];
    const uint32_t sbase = smem_u32(smc);
    const int tid  = threadIdx.x;
    const int lane = tid & 31;
    const int wid  = tid >> 5;           // 0..7
    const int wm   = wid >> 1;           // 0..3  (rows n, 32 each)
    const int wn   = wid & 1;            // 0..1  (cols m, 56 each)
    const int b    = blockIdx.z;
    const int n0   = blockIdx.y * 128;   // rows (theta), padded range
    const int mb0  = blockIdx.x * 112;   // cols (phi)

    float acc[14][4];                    // [i*7+j], i<2 (16-row), j<7 (8-col)
    #pragma unroll
    for (int i = 0; i < 14; i++)
        #pragma unroll
        for (int j = 0; j < 4; j++) acc[i][j] = 0.f;

    auto issue = [&](int kt, int buf) {
        const int k0 = kt * 32;
        const uint32_t st = sbase + buf * G2_STAGE;
        #pragma unroll
        for (int i = 0; i < 2; i++) {    // A: 512 tasks, clamp row to 783
            int t = tid + i * 256;
            int row = t >> 2, ch = t & 3;
            int gn = n0 + row; if (gn > NPOS - 1) gn = NPOS - 1;
            const __half* asrc = g_Th
                + ((size_t)b * NPOS + gn) * CI + k0 + ch * 8;
            cp16(st + row * 80 + ch * 16, asrc);
        }
        #pragma unroll
        for (int i = 0; i < 2; i++) {    // B: 448 tasks
            int t = tid + i * 256;
            if (t < 448) {
                int row = t >> 2, ch = t & 3;
                const __half* bsrc = g_Ph
                    + ((size_t)b * NPOS + mb0 + row) * CI + k0 + ch * 8;
                cp16(st + G2_BOFF + row * 80 + ch * 16, bsrc);
            }
        }
        CP_COMMIT();
    };

    issue(0, 0);
    issue(1, 1);

    const int arow = lane & 15;
    const int ach  = lane >> 4;
    const int brow = ((lane >> 4) << 3) + (lane & 7);
    const int bch  = (lane >> 3) & 1;
    const int brow2 = (lane & 15) & 7;
    const int bch2  = ((lane & 15) >> 3) & 1;

    for (int kt = 0; kt < 16; kt++) {
        CP_WAIT_1();
        __syncthreads();
        const uint32_t st = sbase + (kt & 1) * G2_STAGE;
        #pragma unroll
        for (int s = 0; s < 2; s++) {
            uint32_t ah[2][4], bb[7][2];
            #pragma unroll
            for (int i = 0; i < 2; i++) {
                uint32_t aa = st + (wm * 32 + i * 16 + arow) * 80 + (s * 2 + ach) * 16;
                ldsm_x4(ah[i], aa);
            }
            #pragma unroll
            for (int p = 0; p < 3; p++) {
                uint32_t ba = st + G2_BOFF + (wn * 56 + p * 16 + brow) * 80 + (s * 2 + bch) * 16;
                uint32_t r[4]; ldsm_x4(r, ba);
                bb[p*2][0] = r[0]; bb[p*2][1] = r[1];
                bb[p*2+1][0] = r[2]; bb[p*2+1][1] = r[3];
            }
            ldsm_x2(bb[6][0], bb[6][1],
                    st + G2_BOFF + (wn * 56 + 48 + brow2) * 80 + (s * 2 + bch2) * 16);
            #pragma unroll
            for (int i = 0; i < 2; i++)
                #pragma unroll
                for (int j = 0; j < 7; j++)
                    mma16816(acc[i*7+j], ah[i], bb[j]);
        }
        __syncthreads();
        if (kt + 2 < 16) issue(kt + 2, kt & 1); else CP_COMMIT();
    }

    // epilogue: fp32 bounce [128][116], guarded coalesced float4 stores
    __syncthreads();
    float* eb = reinterpret_cast<float*>(smc);
    #pragma unroll
    for (int i = 0; i < 2; i++)
        #pragma unroll
        for (int j = 0; j < 7; j++) {
            int row = wm * 32 + i * 16 + (lane >> 2);
            int col = wn * 56 + j * 8 + (lane & 3) * 2;
            eb[row * G2_EPITCH + col]           = acc[i*7+j][0];
            eb[row * G2_EPITCH + col + 1]       = acc[i*7+j][1];
            eb[(row + 8) * G2_EPITCH + col]     = acc[i*7+j][2];
            eb[(row + 8) * G2_EPITCH + col + 1] = acc[i*7+j][3];
        }
    __syncthreads();
    #pragma unroll
    for (int i = 0; i < 14; i++) {
        int t = tid + i * 256;          // 0..3583
        int row = t / 28, c4 = t % 28;
        if (n0 + row < NPOS) {
            float4 v = *reinterpret_cast<const float4*>(&eb[row * G2_EPITCH + c4 * 4]);
            *reinterpret_cast<float4*>(
                g_F + ((size_t)b * NPOS + n0 + row) * NPOS + mb0 + c4 * 4) = v;
        }
    }
}

// ===========================================================================
// softmax stats: warp per row, register-resident single DRAM pass
// ===========================================================================
__global__ __launch_bounds__(256) void softmax_stats_kernel()
{
    const int r    = blockIdx.x * 8 + (threadIdx.x >> 5);
    const int lane = threadIdx.x & 31;
    const float4* __restrict__ row4 =
        reinterpret_cast<const float4*>(g_F + (size_t)r * NPOS);

    float4 v[7];
    #pragma unroll
    for (int k = 0; k < 7; k++) {
        int c4 = lane + k * 32;
        if (k < 6 || c4 < 196) v[k] = row4[c4];
        else v[k] = make_float4(-CUDART_INF_F, -CUDART_INF_F, -CUDART_INF_F, -CUDART_INF_F);
    }
    float m = -CUDART_INF_F;
    #pragma unroll
    for (int k = 0; k < 7; k++)
        m = fmaxf(m, fmaxf(fmaxf(v[k].x, v[k].y), fmaxf(v[k].z, v[k].w)));
    #pragma unroll
    for (int o = 16; o; o >>= 1) m = fmaxf(m, __shfl_xor_sync(0xffffffffu, m, o));

    float s = 0.f;
    #pragma unroll
    for (int k = 0; k < 7; k++) {
        s += __expf(v[k].x - m) + __expf(v[k].y - m)
           + __expf(v[k].z - m) + __expf(v[k].w - m);
    }
    #pragma unroll
    for (int o = 16; o; o >>= 1) s += __shfl_xor_sync(0xffffffffu, s, o);

    if (lane == 0) {
        g_rmax[r]   = m;
        g_rscale[r] = 1.f / (s * (float)NPOS);
    }
}

// a_bar[b][m] = sum_n exp(F[n][m]-rmax[n]) * rscale[n]
__global__ __launch_bounds__(112) void colsum_kernel()
{
    const int b  = blockIdx.z;
    const int m  = blockIdx.x * 112 + threadIdx.x;
    const int n0 = blockIdx.y * 112;

    __shared__ float srs[112];
    __shared__ float smx[112];
    srs[threadIdx.x] = g_rscale[b * NPOS + n0 + threadIdx.x];
    smx[threadIdx.x] = g_rmax[b * NPOS + n0 + threadIdx.x];
    __syncthreads();

    const float* __restrict__ Fb = g_F + ((size_t)b * NPOS + n0) * NPOS + m;
    float acc = 0.f;
    #pragma unroll 8
    for (int j = 0; j < 112; j++)
        acc += __expf(Fb[(size_t)j * NPOS] - smx[j]) * srs[j];
    atomicAdd(&g_abar[b * NPOS + m], acc);
}

__global__ __launch_bounds__(256) void xw_kernel(const float* __restrict__ x)
{
    const int b    = blockIdx.y;
    const int c    = blockIdx.x * 8 + (threadIdx.x >> 5);
    const int lane = threadIdx.x & 31;

    __shared__ float sa[NPOS];
    for (int i = threadIdx.x; i < NPOS; i += 256) sa[i] = g_abar[b * NPOS + i];
    __syncthreads();

    const float* __restrict__ xr = x + ((size_t)b * CDIM + c) * NPOS;
    float dot = 0.f, sum = 0.f;
    for (int i = lane; i < NPOS; i += 32) {
        float v = xr[i];
        dot = fmaf(v, sa[i], dot);
        sum += v;
    }
    #pragma unroll
    for (int o = 16; o; o >>= 1) {
        dot += __shfl_xor_sync(0xffffffffu, dot, o);
        sum += __shfl_xor_sync(0xffffffffu, sum, o);
    }
    if (lane == 0) {
        g_xw[b * CDIM + c]   = dot;
        g_xbar[b * CDIM + c] = sum * (1.f / (float)NPOS);
    }
}

__global__ __launch_bounds__(256) void ybar_kernel(const float* __restrict__ Wg,
                                                   const float* __restrict__ bg)
{
    const int b    = blockIdx.y;
    const int i    = blockIdx.x * 8 + (threadIdx.x >> 5);
    const int lane = threadIdx.x & 31;

    __shared__ float sx[CDIM];
    for (int k = threadIdx.x; k < CDIM; k += 256) sx[k] = g_xw[b * CDIM + k];
    __syncthreads();

    const float* __restrict__ w = Wg + (size_t)i * CDIM;
    float d = 0.f;
    for (int k = lane; k < CDIM; k += 32) d = fmaf(w[k], sx[k], d);
    #pragma unroll
    for (int o = 16; o; o >>= 1) d += __shfl_xor_sync(0xffffffffu, d, o);
    if (lane == 0) g_ybar[b * CI + i] = d + bg[i];
}

__global__ __launch_bounds__(256) void pooled_kernel(
    const float* __restrict__ Ww, const float* __restrict__ bw,
    const float* __restrict__ gamma, const float* __restrict__ beta,
    const float* __restrict__ bmean, const float* __restrict__ bvar)
{
    const int b    = blockIdx.y;
    const int c    = blockIdx.x * 8 + (threadIdx.x >> 5);
    const int lane = threadIdx.x & 31;

    __shared__ float sy[CI];
    for (int k = threadIdx.x; k < CI; k += 256) sy[k] = g_ybar[b * CI + k];
    __syncthreads();

    const float* __restrict__ w = Ww + (size_t)c * CI;
    float d = 0.f;
    for (int k = lane; k < CI; k += 32) d = fmaf(w[k], sy[k], d);
    #pragma unroll
    for (int o = 16; o; o >>= 1) d += __shfl_xor_sync(0xffffffffu, d, o);
    if (lane == 0) {
        float inv = gamma[c] * rsqrtf(bvar[c] + 1e-5f);
        g_pooled[b * CDIM + c] =
            inv * (d + bw[c]) + (beta[c] - bmean[c] * inv) + g_xbar[b * CDIM + c];
    }
}

__global__ __launch_bounds__(256) void h_kernel(const float* __restrict__ W1,
                                                const float* __restrict__ b1)
{
    const int b    = blockIdx.y;
    const int j    = blockIdx.x * 8 + (threadIdx.x >> 5);
    const int lane = threadIdx.x & 31;

    __shared__ float sp[CDIM];
    for (int k = threadIdx.x; k < CDIM; k += 256) sp[k] = g_pooled[b * CDIM + k];
    __syncthreads();

    const float* __restrict__ w = W1 + (size_t)j * CDIM;
    float d = 0.f;
    for (int k = lane; k < CDIM; k += 32) d = fmaf(w[k], sp[k], d);
    #pragma unroll
    for (int o = 16; o; o >>= 1) d += __shfl_xor_sync(0xffffffffu, d, o);
    if (lane == 0) g_h[b * CI + j] = d + b1[j];
}

__global__ __launch_bounds__(256) void out_kernel(const float* __restrict__ xface,
                                                  const float* __restrict__ W2,
                                                  const float* __restrict__ b2,
                                                  float* __restrict__ out)
{
    const int b = blockIdx.x;
    const int o = threadIdx.x >> 7;
    const int t = threadIdx.x & 127;

    float acc = 0.f;
    for (int k = t; k < CDIM; k += 128) {
        float v = (k < CI) ? g_h[b * CI + k] : xface[b * CI + (k - CI)];
        acc = fmaf(W2[o * CDIM + k], v, acc);
    }
    #pragma unroll
    for (int off = 16; off; off >>= 1) acc += __shfl_xor_sync(0xffffffffu, acc, off);

    __shared__ float sred[8];
    const int warp = threadIdx.x >> 5;
    if ((threadIdx.x & 31) == 0) sred[warp] = acc;
    __syncthreads();
    if (threadIdx.x == 0)
        out[b * 2 + 0] = sred[0] + sred[1] + sred[2] + sred[3] + b2[0];
    if (threadIdx.x == 128)
        out[b * 2 + 1] = sred[4] + sred[5] + sred[6] + sred[7] + b2[1];
}

// ===========================================================================
extern "C" void kernel_launch(void* const* d_in, const int* in_sizes, int n_in,
                              void* d_out, int out_size)
{
    const float* x_body = (const float*)d_in[0];
    const float* x_face = (const float*)d_in[1];
    const float* Wg     = (const float*)d_in[2];
    const float* bg     = (const float*)d_in[3];
    const float* Wth    = (const float*)d_in[4];
    const float* bth    = (const float*)d_in[5];
    const float* Wph    = (const float*)d_in[6];
    const float* bph    = (const float*)d_in[7];
    const float* Ww     = (const float*)d_in[8];
    const float* bw     = (const float*)d_in[9];
    const float* gamma  = (const float*)d_in[10];
    const float* beta   = (const float*)d_in[11];
    const float* bmean  = (const float*)d_in[12];
    const float* bvar   = (const float*)d_in[13];
    const float* W1     = (const float*)d_in[14];
    const float* b1     = (const float*)d_in[15];
    const float* W2     = (const float*)d_in[16];
    const float* b2     = (const float*)d_in[17];
    float* out = (float*)d_out;

    cudaFuncSetAttribute(gemm1_mma, cudaFuncAttributeMaxDynamicSharedMemorySize, G1_SMEM);
    cudaFuncSetAttribute(gemm2_mma, cudaFuncAttributeMaxDynamicSharedMemorySize, G2_SMEM);

    convert_W_kernel<<<(CDIM * CDIM) / 256, 256>>>(Wth, Wph);
    convert_X_kernel<<<dim3((NPOS + 31) / 32, CDIM / 32, BATCH), 256>>>(x_body);

    gemm1_mma<<<dim3(NPOS / 112, CDIM / 128, BATCH), 128, G1_SMEM>>>(bth, bph);
    gemm2_mma<<<dim3(NPOS / 112, (NPOS + 127) / 128, BATCH), 256, G2_SMEM>>>();

    softmax_stats_kernel<<<BATCH * NPOS / 8, 256>>>();
    colsum_kernel<<<dim3(NPOS / 112, NPOS / 112, BATCH), 112>>>();
    xw_kernel<<<dim3(CDIM / 8, BATCH), 256>>>(x_body);
    ybar_kernel<<<dim3(CI / 8, BATCH), 256>>>(Wg, bg);
    pooled_kernel<<<dim3(CDIM / 8, BATCH), 256>>>(Ww, bw, gamma, beta, bmean, bvar);
    h_kernel<<<dim3(CI / 8, BATCH), 256>>>(W1, b1);
    out_kernel<<<BATCH, 256>>>(x_face, W2, b2, out);
}

// round 9
// speedup vs baseline: 5.3962x; 1.0305x over previous
#include <cuda_runtime.h>
#include <cuda_fp16.h>
#include <math_constants.h>
#include <cstdint>

#define BATCH 32
#define CDIM  1024
#define CI    512
#define NPOS  784

// -------- scratch (device globals) --------
__device__ __align__(16) __half g_Wh[(size_t)CDIM * CDIM];          // W fp16 (theta rows 0..511, phi 512..1023)
__device__ __align__(16) __half g_Xt[(size_t)BATCH * NPOS * CDIM];  // X^T fp16 [b][n][c]
__device__ __align__(16) __half g_Th[(size_t)BATCH * NPOS * CI];    // theta^T fp16 [b][n][k]
__device__ __align__(16) __half g_Ph[(size_t)BATCH * NPOS * CI];    // phi^T fp16
__device__ __align__(16) float g_F[(size_t)BATCH * NPOS * NPOS];    // raw logits
__device__ float g_rmax[BATCH * NPOS];
__device__ float g_rscale[BATCH * NPOS];
__device__ float g_abar[BATCH * NPOS];
__device__ float g_xw[BATCH * CDIM];
__device__ float g_xbar[BATCH * CDIM];
__device__ float g_ybar[BATCH * CI];
__device__ float g_pooled[BATCH * CDIM];
__device__ float g_h[BATCH * CI];

// -------- helpers --------
__device__ __forceinline__ uint32_t smem_u32(const void* p) {
    uint32_t a;
    asm("{ .reg .u64 t; cvta.to.shared.u64 t, %1; cvt.u32.u64 %0, t; }" : "=r"(a) : "l"(p));
    return a;
}
__device__ __forceinline__ void cp16(uint32_t dst, const void* src) {
    asm volatile("cp.async.cg.shared.global [%0], [%1], 16;" :: "r"(dst), "l"(src) : "memory");
}
#define CP_COMMIT() asm volatile("cp.async.commit_group;" ::: "memory")
#define CP_WAIT_2() asm volatile("cp.async.wait_group 2;" ::: "memory")

__device__ __forceinline__ void ldsm_x4(uint32_t (&r)[4], uint32_t a) {
    asm volatile("ldmatrix.sync.aligned.m8n8.x4.shared.b16 {%0,%1,%2,%3}, [%4];"
                 : "=r"(r[0]), "=r"(r[1]), "=r"(r[2]), "=r"(r[3]) : "r"(a));
}
__device__ __forceinline__ void ldsm_x2(uint32_t& r0, uint32_t& r1, uint32_t a) {
    asm volatile("ldmatrix.sync.aligned.m8n8.x2.shared.b16 {%0,%1}, [%2];"
                 : "=r"(r0), "=r"(r1) : "r"(a));
}
__device__ __forceinline__ void mma16816(float* c, const uint32_t* a, const uint32_t* b) {
    asm volatile(
        "mma.sync.aligned.m16n8k16.row.col.f32.f16.f16.f32 "
        "{%0,%1,%2,%3}, {%4,%5,%6,%7}, {%8,%9}, {%0,%1,%2,%3};"
        : "+f"(c[0]), "+f"(c[1]), "+f"(c[2]), "+f"(c[3])
        : "r"(a[0]), "r"(a[1]), "r"(a[2]), "r"(a[3]), "r"(b[0]), "r"(b[1]));
}

// ===========================================================================
// conversions
// ===========================================================================
__global__ __launch_bounds__(256) void convert_W_kernel(
    const float* __restrict__ Wth, const float* __restrict__ Wph)
{
    int i = blockIdx.x * 256 + threadIdx.x;
    float w = (i < CI * CDIM) ? Wth[i] : Wph[i - CI * CDIM];
    g_Wh[i] = __float2half(w);
    if (i < BATCH * NPOS) g_abar[i] = 0.f;
}

__global__ __launch_bounds__(256) void convert_X_kernel(const float* __restrict__ x)
{
    __shared__ float tile[32][33];
    const int b  = blockIdx.z;
    const int c0 = blockIdx.y * 32;
    const int n0 = blockIdx.x * 32;
    const int tx = threadIdx.x & 31;
    const int ty = threadIdx.x >> 5;

    #pragma unroll
    for (int i = 0; i < 4; i++) {
        int c = c0 + ty + i * 8;
        int n = n0 + tx;
        tile[ty + i * 8][tx] = (n < NPOS) ? x[((size_t)b * CDIM + c) * NPOS + n] : 0.f;
    }
    __syncthreads();
    #pragma unroll
    for (int i = 0; i < 4; i++) {
        int n = n0 + ty + i * 8;
        int c = c0 + tx;
        if (n < NPOS)
            g_Xt[((size_t)b * NPOS + n) * CDIM + c] = __float2half(tile[tx][ty + i * 8]);
    }
}

// ===========================================================================
// GEMM1 (warp MMA, fp16): C[m][n] = sum_k W[m][k] X^T[n][k]
// CTA tile 128x112, 4 warps (2M x 2N), warp tile 64x56.
// 3-stage cp.async pipeline (2 iterations of prefetch distance).
// SMEM: max(3*19200 pipeline, 112*144*2 bounce) = 57600 -> 3 CTA/SM
// ===========================================================================
#define G1_BOFF  10240           // A: 128 rows * 80B
#define G1_STAGE 19200           // + B: 112 rows * 80B
#define G1_SMEM  57600
#define G1_EPITCH 144            // halves per n-row in epilogue bounce

__global__ __launch_bounds__(128, 3) void gemm1_mma(
    const float* __restrict__ bth, const float* __restrict__ bph)
{
    extern __shared__ char smc[];
    const uint32_t sbase = smem_u32(smc);
    const int tid  = threadIdx.x;
    const int lane = tid & 31;
    const int wid  = tid >> 5;           // 0..3
    const int wm   = wid >> 1;           // 0..1  (M, 64 rows)
    const int wn   = wid & 1;            // 0..1  (N, 56 cols)
    const int b    = blockIdx.z;
    const int m0   = blockIdx.y * 128;
    const int n0   = blockIdx.x * 112;

    float acc[28][4];                    // [i*7+j], i<4 (16-row frag), j<7 (8-col frag)
    #pragma unroll
    for (int i = 0; i < 28; i++)
        #pragma unroll
        for (int j = 0; j < 4; j++) acc[i][j] = 0.f;

    auto issue = [&](int kt, int buf) {
        const int k0 = kt * 32;
        const uint32_t st = sbase + buf * G1_STAGE;
        #pragma unroll
        for (int i = 0; i < 4; i++) {           // A: 512 tasks
            int t = tid + i * 128;
            int row = t >> 2, ch = t & 3;
            const __half* src = g_Wh + (size_t)(m0 + row) * CDIM + k0 + ch * 8;
            cp16(st + row * 80 + ch * 16, src);
        }
        #pragma unroll
        for (int i = 0; i < 4; i++) {           // B: 448 tasks
            int t = tid + i * 128;
            if (t < 448) {
                int row = t >> 2, ch = t & 3;
                const __half* src = g_Xt
                    + ((size_t)b * NPOS + n0 + row) * CDIM + k0 + ch * 8;
                cp16(st + G1_BOFF + row * 80 + ch * 16, src);
            }
        }
        CP_COMMIT();
    };

    issue(0, 0);
    issue(1, 1);
    issue(2, 2);

    const int arow = lane & 15;
    const int ach  = lane >> 4;
    const int brow = ((lane >> 4) << 3) + (lane & 7);
    const int bch  = (lane >> 3) & 1;
    const int brow2 = (lane & 15) & 7;
    const int bch2  = ((lane & 15) >> 3) & 1;

    int buf = 0, pbuf = 0;               // compute buffer, next prefetch buffer
    for (int kt = 0; kt < 32; kt++) {
        CP_WAIT_2();
        __syncthreads();
        const uint32_t st = sbase + buf * G1_STAGE;
        #pragma unroll
        for (int s = 0; s < 2; s++) {
            uint32_t ah[4][4], bb[7][2];
            #pragma unroll
            for (int p = 0; p < 3; p++) {
                uint32_t ba = st + G1_BOFF + (wn * 56 + p * 16 + brow) * 80 + (s * 2 + bch) * 16;
                uint32_t r[4]; ldsm_x4(r, ba);
                bb[p*2][0] = r[0]; bb[p*2][1] = r[1];
                bb[p*2+1][0] = r[2]; bb[p*2+1][1] = r[3];
            }
            ldsm_x2(bb[6][0], bb[6][1],
                    st + G1_BOFF + (wn * 56 + 48 + brow2) * 80 + (s * 2 + bch2) * 16);
            #pragma unroll
            for (int i = 0; i < 4; i++) {
                uint32_t aa = st + (wm * 64 + i * 16 + arow) * 80 + (s * 2 + ach) * 16;
                ldsm_x4(ah[i], aa);
            }
            #pragma unroll
            for (int i = 0; i < 4; i++)
                #pragma unroll
                for (int j = 0; j < 7; j++)
                    mma16816(acc[i*7+j], ah[i], bb[j]);
        }
        __syncthreads();
        if (kt + 3 < 32) issue(kt + 3, pbuf); else CP_COMMIT();
        buf  = (buf == 2)  ? 0 : buf + 1;
        pbuf = (pbuf == 2) ? 0 : pbuf + 1;
    }

    // ---- epilogue: fp16 bounce [n][ch] pitch 144, then uint4 biased stores
    __syncthreads();
    __half* eb = reinterpret_cast<__half*>(smc);
    #pragma unroll
    for (int i = 0; i < 4; i++)
        #pragma unroll
        for (int j = 0; j < 7; j++) {
            int ch  = wm * 64 + i * 16 + (lane >> 2);
            int col = wn * 56 + j * 8 + (lane & 3) * 2;
            eb[col * G1_EPITCH + ch]           = __float2half(acc[i*7+j][0]);
            eb[(col + 1) * G1_EPITCH + ch]     = __float2half(acc[i*7+j][1]);
            eb[col * G1_EPITCH + ch + 8]       = __float2half(acc[i*7+j][2]);
            eb[(col + 1) * G1_EPITCH + ch + 8] = __float2half(acc[i*7+j][3]);
        }
    __syncthreads();

    const bool isTheta = (m0 < CI);
    __half* dst = isTheta ? g_Th : g_Ph;
    const int ch0g = isTheta ? m0 : (m0 - CI);
    const float* bias = isTheta ? bth : bph;

    #pragma unroll
    for (int it = 0; it < 14; it++) {
        int t  = tid + it * 128;       // 0..1791
        int cg = t & 15, n = t >> 4;
        int chl = cg * 8;
        uint4 raw = *reinterpret_cast<const uint4*>(eb + n * G1_EPITCH + chl);
        const __half* rh = reinterpret_cast<const __half*>(&raw);
        __align__(16) __half h8[8];
        #pragma unroll
        for (int k = 0; k < 8; k++)
            h8[k] = __float2half(__half2float(rh[k]) + bias[ch0g + chl + k]);
        size_t off = ((size_t)b * NPOS + n0 + n) * CI + ch0g + chl;
        *reinterpret_cast<uint4*>(dst + off) = *reinterpret_cast<const uint4*>(h8);
    }
}

// ===========================================================================
// GEMM2 (warp MMA, fp16): F[n][m] = sum_k Th[n][k] Ph[m][k]
// CTA tile 128(n, clamped at 784) x 112(m), 8 warps (4M x 2N), warp 32x56.
// 3-stage cp.async pipeline.
// SMEM: max(3*19200=57600, 128*116*4=59392 fp32 epilogue) = 59392
// ===========================================================================
#define G2_BOFF  10240           // A: 128 rows * 80B
#define G2_STAGE 19200           // + B: 112 rows * 80B
#define G2_SMEM  59392
#define G2_EPITCH 116

__global__ __launch_bounds__(256, 2) void gemm2_mma()
{
    extern __shared__ char smc[];
    const uint32_t sbase = smem_u32(smc);
    const int tid  = threadIdx.x;
    const int lane = tid & 31;
    const int wid  = tid >> 5;           // 0..7
    const int wm   = wid >> 1;           // 0..3  (rows n, 32 each)
    const int wn   = wid & 1;            // 0..1  (cols m, 56 each)
    const int b    = blockIdx.z;
    const int n0   = blockIdx.y * 128;   // rows (theta), padded range
    const int mb0  = blockIdx.x * 112;   // cols (phi)

    float acc[14][4];                    // [i*7+j], i<2 (16-row), j<7 (8-col)
    #pragma unroll
    for (int i = 0; i < 14; i++)
        #pragma unroll
        for (int j = 0; j < 4; j++) acc[i][j] = 0.f;

    auto issue = [&](int kt, int buf) {
        const int k0 = kt * 32;
        const uint32_t st = sbase + buf * G2_STAGE;
        #pragma unroll
        for (int i = 0; i < 2; i++) {    // A: 512 tasks, clamp row to 783
            int t = tid + i * 256;
            int row = t >> 2, ch = t & 3;
            int gn = n0 + row; if (gn > NPOS - 1) gn = NPOS - 1;
            const __half* asrc = g_Th
                + ((size_t)b * NPOS + gn) * CI + k0 + ch * 8;
            cp16(st + row * 80 + ch * 16, asrc);
        }
        #pragma unroll
        for (int i = 0; i < 2; i++) {    // B: 448 tasks
            int t = tid + i * 256;
            if (t < 448) {
                int row = t >> 2, ch = t & 3;
                const __half* bsrc = g_Ph
                    + ((size_t)b * NPOS + mb0 + row) * CI + k0 + ch * 8;
                cp16(st + G2_BOFF + row * 80 + ch * 16, bsrc);
            }
        }
        CP_COMMIT();
    };

    issue(0, 0);
    issue(1, 1);
    issue(2, 2);

    const int arow = lane & 15;
    const int ach  = lane >> 4;
    const int brow = ((lane >> 4) << 3) + (lane & 7);
    const int bch  = (lane >> 3) & 1;
    const int brow2 = (lane & 15) & 7;
    const int bch2  = ((lane & 15) >> 3) & 1;

    int buf = 0, pbuf = 0;
    for (int kt = 0; kt < 16; kt++) {
        CP_WAIT_2();
        __syncthreads();
        const uint32_t st = sbase + buf * G2_STAGE;
        #pragma unroll
        for (int s = 0; s < 2; s++) {
            uint32_t ah[2][4], bb[7][2];
            #pragma unroll
            for (int i = 0; i < 2; i++) {
                uint32_t aa = st + (wm * 32 + i * 16 + arow) * 80 + (s * 2 + ach) * 16;
                ldsm_x4(ah[i], aa);
            }
            #pragma unroll
            for (int p = 0; p < 3; p++) {
                uint32_t ba = st + G2_BOFF + (wn * 56 + p * 16 + brow) * 80 + (s * 2 + bch) * 16;
                uint32_t r[4]; ldsm_x4(r, ba);
                bb[p*2][0] = r[0]; bb[p*2][1] = r[1];
                bb[p*2+1][0] = r[2]; bb[p*2+1][1] = r[3];
            }
            ldsm_x2(bb[6][0], bb[6][1],
                    st + G2_BOFF + (wn * 56 + 48 + brow2) * 80 + (s * 2 + bch2) * 16);
            #pragma unroll
            for (int i = 0; i < 2; i++)
                #pragma unroll
                for (int j = 0; j < 7; j++)
                    mma16816(acc[i*7+j], ah[i], bb[j]);
        }
        __syncthreads();
        if (kt + 3 < 16) issue(kt + 3, pbuf); else CP_COMMIT();
        buf  = (buf == 2)  ? 0 : buf + 1;
        pbuf = (pbuf == 2) ? 0 : pbuf + 1;
    }

    // epilogue: fp32 bounce [128][116], guarded coalesced float4 stores
    __syncthreads();
    float* eb = reinterpret_cast<float*>(smc);
    #pragma unroll
    for (int i = 0; i < 2; i++)
        #pragma unroll
        for (int j = 0; j < 7; j++) {
            int row = wm * 32 + i * 16 + (lane >> 2);
            int col = wn * 56 + j * 8 + (lane & 3) * 2;
            eb[row * G2_EPITCH + col]           = acc[i*7+j][0];
            eb[row * G2_EPITCH + col + 1]       = acc[i*7+j][1];
            eb[(row + 8) * G2_EPITCH + col]     = acc[i*7+j][2];
            eb[(row + 8) * G2_EPITCH + col + 1] = acc[i*7+j][3];
        }
    __syncthreads();
    #pragma unroll
    for (int i = 0; i < 14; i++) {
        int t = tid + i * 256;          // 0..3583
        int row = t / 28, c4 = t % 28;
        if (n0 + row < NPOS) {
            float4 v = *reinterpret_cast<const float4*>(&eb[row * G2_EPITCH + c4 * 4]);
            *reinterpret_cast<float4*>(
                g_F + ((size_t)b * NPOS + n0 + row) * NPOS + mb0 + c4 * 4) = v;
        }
    }
}

// ===========================================================================
// softmax stats: warp per row, register-resident single DRAM pass
// ===========================================================================
__global__ __launch_bounds__(256) void softmax_stats_kernel()
{
    const int r    = blockIdx.x * 8 + (threadIdx.x >> 5);
    const int lane = threadIdx.x & 31;
    const float4* __restrict__ row4 =
        reinterpret_cast<const float4*>(g_F + (size_t)r * NPOS);

    float4 v[7];
    #pragma unroll
    for (int k = 0; k < 7; k++) {
        int c4 = lane + k * 32;
        if (k < 6 || c4 < 196) v[k] = row4[c4];
        else v[k] = make_float4(-CUDART_INF_F, -CUDART_INF_F, -CUDART_INF_F, -CUDART_INF_F);
    }
    float m = -CUDART_INF_F;
    #pragma unroll
    for (int k = 0; k < 7; k++)
        m = fmaxf(m, fmaxf(fmaxf(v[k].x, v[k].y), fmaxf(v[k].z, v[k].w)));
    #pragma unroll
    for (int o = 16; o; o >>= 1) m = fmaxf(m, __shfl_xor_sync(0xffffffffu, m, o));

    float s = 0.f;
    #pragma unroll
    for (int k = 0; k < 7; k++) {
        s += __expf(v[k].x - m) + __expf(v[k].y - m)
           + __expf(v[k].z - m) + __expf(v[k].w - m);
    }
    #pragma unroll
    for (int o = 16; o; o >>= 1) s += __shfl_xor_sync(0xffffffffu, s, o);

    if (lane == 0) {
        g_rmax[r]   = m;
        g_rscale[r] = 1.f / (s * (float)NPOS);
    }
}

// a_bar[b][m] = sum_n exp(F[n][m]-rmax[n]) * rscale[n]
__global__ __launch_bounds__(112) void colsum_kernel()
{
    const int b  = blockIdx.z;
    const int m  = blockIdx.x * 112 + threadIdx.x;
    const int n0 = blockIdx.y * 112;

    __shared__ float srs[112];
    __shared__ float smx[112];
    srs[threadIdx.x] = g_rscale[b * NPOS + n0 + threadIdx.x];
    smx[threadIdx.x] = g_rmax[b * NPOS + n0 + threadIdx.x];
    __syncthreads();

    const float* __restrict__ Fb = g_F + ((size_t)b * NPOS + n0) * NPOS + m;
    float acc = 0.f;
    #pragma unroll 8
    for (int j = 0; j < 112; j++)
        acc += __expf(Fb[(size_t)j * NPOS] - smx[j]) * srs[j];
    atomicAdd(&g_abar[b * NPOS + m], acc);
}

__global__ __launch_bounds__(256) void xw_kernel(const float* __restrict__ x)
{
    const int b    = blockIdx.y;
    const int c    = blockIdx.x * 8 + (threadIdx.x >> 5);
    const int lane = threadIdx.x & 31;

    __shared__ float sa[NPOS];
    for (int i = threadIdx.x; i < NPOS; i += 256) sa[i] = g_abar[b * NPOS + i];
    __syncthreads();

    const float* __restrict__ xr = x + ((size_t)b * CDIM + c) * NPOS;
    float dot = 0.f, sum = 0.f;
    for (int i = lane; i < NPOS; i += 32) {
        float v = xr[i];
        dot = fmaf(v, sa[i], dot);
        sum += v;
    }
    #pragma unroll
    for (int o = 16; o; o >>= 1) {
        dot += __shfl_xor_sync(0xffffffffu, dot, o);
        sum += __shfl_xor_sync(0xffffffffu, sum, o);
    }
    if (lane == 0) {
        g_xw[b * CDIM + c]   = dot;
        g_xbar[b * CDIM + c] = sum * (1.f / (float)NPOS);
    }
}

__global__ __launch_bounds__(256) void ybar_kernel(const float* __restrict__ Wg,
                                                   const float* __restrict__ bg)
{
    const int b    = blockIdx.y;
    const int i    = blockIdx.x * 8 + (threadIdx.x >> 5);
    const int lane = threadIdx.x & 31;

    __shared__ float sx[CDIM];
    for (int k = threadIdx.x; k < CDIM; k += 256) sx[k] = g_xw[b * CDIM + k];
    __syncthreads();

    const float* __restrict__ w = Wg + (size_t)i * CDIM;
    float d = 0.f;
    for (int k = lane; k < CDIM; k += 32) d = fmaf(w[k], sx[k], d);
    #pragma unroll
    for (int o = 16; o; o >>= 1) d += __shfl_xor_sync(0xffffffffu, d, o);
    if (lane == 0) g_ybar[b * CI + i] = d + bg[i];
}

__global__ __launch_bounds__(256) void pooled_kernel(
    const float* __restrict__ Ww, const float* __restrict__ bw,
    const float* __restrict__ gamma, const float* __restrict__ beta,
    const float* __restrict__ bmean, const float* __restrict__ bvar)
{
    const int b    = blockIdx.y;
    const int c    = blockIdx.x * 8 + (threadIdx.x >> 5);
    const int lane = threadIdx.x & 31;

    __shared__ float sy[CI];
    for (int k = threadIdx.x; k < CI; k += 256) sy[k] = g_ybar[b * CI + k];
    __syncthreads();

    const float* __restrict__ w = Ww + (size_t)c * CI;
    float d = 0.f;
    for (int k = lane; k < CI; k += 32) d = fmaf(w[k], sy[k], d);
    #pragma unroll
    for (int o = 16; o; o >>= 1) d += __shfl_xor_sync(0xffffffffu, d, o);
    if (lane == 0) {
        float inv = gamma[c] * rsqrtf(bvar[c] + 1e-5f);
        g_pooled[b * CDIM + c] =
            inv * (d + bw[c]) + (beta[c] - bmean[c] * inv) + g_xbar[b * CDIM + c];
    }
}

__global__ __launch_bounds__(256) void h_kernel(const float* __restrict__ W1,
                                                const float* __restrict__ b1)
{
    const int b    = blockIdx.y;
    const int j    = blockIdx.x * 8 + (threadIdx.x >> 5);
    const int lane = threadIdx.x & 31;

    __shared__ float sp[CDIM];
    for (int k = threadIdx.x; k < CDIM; k += 256) sp[k] = g_pooled[b * CDIM + k];
    __syncthreads();

    const float* __restrict__ w = W1 + (size_t)j * CDIM;
    float d = 0.f;
    for (int k = lane; k < CDIM; k += 32) d = fmaf(w[k], sp[k], d);
    #pragma unroll
    for (int o = 16; o; o >>= 1) d += __shfl_xor_sync(0xffffffffu, d, o);
    if (lane == 0) g_h[b * CI + j] = d + b1[j];
}

__global__ __launch_bounds__(256) void out_kernel(const float* __restrict__ xface,
                                                  const float* __restrict__ W2,
                                                  const float* __restrict__ b2,
                                                  float* __restrict__ out)
{
    const int b = blockIdx.x;
    const int o = threadIdx.x >> 7;
    const int t = threadIdx.x & 127;

    float acc = 0.f;
    for (int k = t; k < CDIM; k += 128) {
        float v = (k < CI) ? g_h[b * CI + k] : xface[b * CI + (k - CI)];
        acc = fmaf(W2[o * CDIM + k], v, acc);
    }
    #pragma unroll
    for (int off = 16; off; off >>= 1) acc += __shfl_xor_sync(0xffffffffu, acc, off);

    __shared__ float sred[8];
    const int warp = threadIdx.x >> 5;
    if ((threadIdx.x & 31) == 0) sred[warp] = acc;
    __syncthreads();
    if (threadIdx.x == 0)
        out[b * 2 + 0] = sred[0] + sred[1] + sred[2] + sred[3] + b2[0];
    if (threadIdx.x == 128)
        out[b * 2 + 1] = sred[4] + sred[5] + sred[6] + sred[7] + b2[1];
}

// ===========================================================================
extern "C" void kernel_launch(void* const* d_in, const int* in_sizes, int n_in,
                              void* d_out, int out_size)
{
    const float* x_body = (const float*)d_in[0];
    const float* x_face = (const float*)d_in[1];
    const float* Wg     = (const float*)d_in[2];
    const float* bg     = (const float*)d_in[3];
    const float* Wth    = (const float*)d_in[4];
    const float* bth    = (const float*)d_in[5];
    const float* Wph    = (const float*)d_in[6];
    const float* bph    = (const float*)d_in[7];
    const float* Ww     = (const float*)d_in[8];
    const float* bw     = (const float*)d_in[9];
    const float* gamma  = (const float*)d_in[10];
    const float* beta   = (const float*)d_in[11];
    const float* bmean  = (const float*)d_in[12];
    const float* bvar   = (const float*)d_in[13];
    const float* W1     = (const float*)d_in[14];
    const float* b1     = (const float*)d_in[15];
    const float* W2     = (const float*)d_in[16];
    const float* b2     = (const float*)d_in[17];
    float* out = (float*)d_out;

    cudaFuncSetAttribute(gemm1_mma, cudaFuncAttributeMaxDynamicSharedMemorySize, G1_SMEM);
    cudaFuncSetAttribute(gemm2_mma, cudaFuncAttributeMaxDynamicSharedMemorySize, G2_SMEM);

    convert_W_kernel<<<(CDIM * CDIM) / 256, 256>>>(Wth, Wph);
    convert_X_kernel<<<dim3((NPOS + 31) / 32, CDIM / 32, BATCH), 256>>>(x_body);

    gemm1_mma<<<dim3(NPOS / 112, CDIM / 128, BATCH), 128, G1_SMEM>>>(bth, bph);
    gemm2_mma<<<dim3(NPOS / 112, (NPOS + 127) / 128, BATCH), 256, G2_SMEM>>>();

    softmax_stats_kernel<<<BATCH * NPOS / 8, 256>>>();
    colsum_kernel<<<dim3(NPOS / 112, NPOS / 112, BATCH), 112>>>();
    xw_kernel<<<dim3(CDIM / 8, BATCH), 256>>>(x_body);
    ybar_kernel<<<dim3(CI / 8, BATCH), 256>>>(Wg, bg);
    pooled_kernel<<<dim3(CDIM / 8, BATCH), 256>>>(Ww, bw, gamma, beta, bmean, bvar);
    h_kernel<<<dim3(CI / 8, BATCH), 256>>>(W1, b1);
    out_kernel<<<BATCH, 256>>>(x_face, W2, b2, out);
}

// round 10
// speedup vs baseline: 5.4940x; 1.0181x over previous
#include <cuda_runtime.h>
#include <cuda_fp16.h>
#include <math_constants.h>
#include <cstdint>

#define BATCH 32
#define CDIM  1024
#define CI    512
#define NPOS  784

// -------- scratch (device globals) --------
__device__ __align__(16) __half g_Wh[(size_t)CDIM * CDIM];          // W fp16 (theta rows 0..511, phi 512..1023)
__device__ __align__(16) __half g_Xt[(size_t)BATCH * NPOS * CDIM];  // X^T fp16 [b][n][c]
__device__ __align__(16) __half g_Th[(size_t)BATCH * NPOS * CI];    // theta^T fp16 [b][n][k]
__device__ __align__(16) __half g_Ph[(size_t)BATCH * NPOS * CI];    // phi^T fp16
__device__ __align__(16) float g_F[(size_t)BATCH * NPOS * NPOS];    // raw logits
__device__ float g_pmax[BATCH * 7 * NPOS];   // per-colblock row max
__device__ float g_psum[BATCH * 7 * NPOS];   // per-colblock row sumexp
__device__ float g_rmax[BATCH * NPOS];
__device__ float g_rscale[BATCH * NPOS];
__device__ float g_abar[BATCH * NPOS];
__device__ float g_xw[BATCH * CDIM];
__device__ float g_xbar[BATCH * CDIM];
__device__ float g_ybar[BATCH * CI];
__device__ float g_pooled[BATCH * CDIM];
__device__ float g_h[BATCH * CI];

// -------- helpers --------
__device__ __forceinline__ uint32_t smem_u32(const void* p) {
    uint32_t a;
    asm("{ .reg .u64 t; cvta.to.shared.u64 t, %1; cvt.u32.u64 %0, t; }" : "=r"(a) : "l"(p));
    return a;
}
__device__ __forceinline__ void cp16(uint32_t dst, const void* src) {
    asm volatile("cp.async.cg.shared.global [%0], [%1], 16;" :: "r"(dst), "l"(src) : "memory");
}
#define CP_COMMIT() asm volatile("cp.async.commit_group;" ::: "memory")
#define CP_WAIT_1() asm volatile("cp.async.wait_group 1;" ::: "memory")
#define CP_WAIT_2() asm volatile("cp.async.wait_group 2;" ::: "memory")

__device__ __forceinline__ void ldsm_x4(uint32_t (&r)[4], uint32_t a) {
    asm volatile("ldmatrix.sync.aligned.m8n8.x4.shared.b16 {%0,%1,%2,%3}, [%4];"
                 : "=r"(r[0]), "=r"(r[1]), "=r"(r[2]), "=r"(r[3]) : "r"(a));
}
__device__ __forceinline__ void ldsm_x2(uint32_t& r0, uint32_t& r1, uint32_t a) {
    asm volatile("ldmatrix.sync.aligned.m8n8.x2.shared.b16 {%0,%1}, [%2];"
                 : "=r"(r0), "=r"(r1) : "r"(a));
}
__device__ __forceinline__ void mma16816(float* c, const uint32_t* a, const uint32_t* b) {
    asm volatile(
        "mma.sync.aligned.m16n8k16.row.col.f32.f16.f16.f32 "
        "{%0,%1,%2,%3}, {%4,%5,%6,%7}, {%8,%9}, {%0,%1,%2,%3};"
        : "+f"(c[0]), "+f"(c[1]), "+f"(c[2]), "+f"(c[3])
        : "r"(a[0]), "r"(a[1]), "r"(a[2]), "r"(a[3]), "r"(b[0]), "r"(b[1]));
}

// ===========================================================================
// conversions
// ===========================================================================
__global__ __launch_bounds__(256) void convert_W_kernel(
    const float* __restrict__ Wth, const float* __restrict__ Wph)
{
    int i = blockIdx.x * 256 + threadIdx.x;
    float w = (i < CI * CDIM) ? Wth[i] : Wph[i - CI * CDIM];
    g_Wh[i] = __float2half(w);
    if (i < BATCH * NPOS) g_abar[i] = 0.f;
}

__global__ __launch_bounds__(256) void convert_X_kernel(const float* __restrict__ x)
{
    __shared__ float tile[32][33];
    const int b  = blockIdx.z;
    const int c0 = blockIdx.y * 32;
    const int n0 = blockIdx.x * 32;
    const int tx = threadIdx.x & 31;
    const int ty = threadIdx.x >> 5;

    #pragma unroll
    for (int i = 0; i < 4; i++) {
        int c = c0 + ty + i * 8;
        int n = n0 + tx;
        tile[ty + i * 8][tx] = (n < NPOS) ? x[((size_t)b * CDIM + c) * NPOS + n] : 0.f;
    }
    __syncthreads();
    #pragma unroll
    for (int i = 0; i < 4; i++) {
        int n = n0 + ty + i * 8;
        int c = c0 + tx;
        if (n < NPOS)
            g_Xt[((size_t)b * NPOS + n) * CDIM + c] = __float2half(tile[tx][ty + i * 8]);
    }
}

// ===========================================================================
// GEMM1 (warp MMA, fp16): C[m][n] = sum_k W[m][k] X^T[n][k]
// CTA tile 128x112, 4 warps (2M x 2N), warp tile 64x56.
// 3-stage cp.async pipeline (K=32 stages).
// ===========================================================================
#define G1_BOFF  10240           // A: 128 rows * 80B
#define G1_STAGE 19200           // + B: 112 rows * 80B
#define G1_SMEM  57600
#define G1_EPITCH 144            // halves per n-row in epilogue bounce

__global__ __launch_bounds__(128, 3) void gemm1_mma(
    const float* __restrict__ bth, const float* __restrict__ bph)
{
    extern __shared__ char smc[];
    const uint32_t sbase = smem_u32(smc);
    const int tid  = threadIdx.x;
    const int lane = tid & 31;
    const int wid  = tid >> 5;           // 0..3
    const int wm   = wid >> 1;           // 0..1  (M, 64 rows)
    const int wn   = wid & 1;            // 0..1  (N, 56 cols)
    const int b    = blockIdx.z;
    const int m0   = blockIdx.y * 128;
    const int n0   = blockIdx.x * 112;

    float acc[28][4];
    #pragma unroll
    for (int i = 0; i < 28; i++)
        #pragma unroll
        for (int j = 0; j < 4; j++) acc[i][j] = 0.f;

    auto issue = [&](int kt, int buf) {
        const int k0 = kt * 32;
        const uint32_t st = sbase + buf * G1_STAGE;
        #pragma unroll
        for (int i = 0; i < 4; i++) {           // A: 512 tasks
            int t = tid + i * 128;
            int row = t >> 2, ch = t & 3;
            const __half* src = g_Wh + (size_t)(m0 + row) * CDIM + k0 + ch * 8;
            cp16(st + row * 80 + ch * 16, src);
        }
        #pragma unroll
        for (int i = 0; i < 4; i++) {           // B: 448 tasks
            int t = tid + i * 128;
            if (t < 448) {
                int row = t >> 2, ch = t & 3;
                const __half* src = g_Xt
                    + ((size_t)b * NPOS + n0 + row) * CDIM + k0 + ch * 8;
                cp16(st + G1_BOFF + row * 80 + ch * 16, src);
            }
        }
        CP_COMMIT();
    };

    issue(0, 0);
    issue(1, 1);
    issue(2, 2);

    const int arow = lane & 15;
    const int ach  = lane >> 4;
    const int brow = ((lane >> 4) << 3) + (lane & 7);
    const int bch  = (lane >> 3) & 1;
    const int brow2 = (lane & 15) & 7;
    const int bch2  = ((lane & 15) >> 3) & 1;

    int buf = 0, pbuf = 0;
    for (int kt = 0; kt < 32; kt++) {
        CP_WAIT_2();
        __syncthreads();
        const uint32_t st = sbase + buf * G1_STAGE;
        #pragma unroll
        for (int s = 0; s < 2; s++) {
            uint32_t ah[4][4], bb[7][2];
            #pragma unroll
            for (int p = 0; p < 3; p++) {
                uint32_t ba = st + G1_BOFF + (wn * 56 + p * 16 + brow) * 80 + (s * 2 + bch) * 16;
                uint32_t r[4]; ldsm_x4(r, ba);
                bb[p*2][0] = r[0]; bb[p*2][1] = r[1];
                bb[p*2+1][0] = r[2]; bb[p*2+1][1] = r[3];
            }
            ldsm_x2(bb[6][0], bb[6][1],
                    st + G1_BOFF + (wn * 56 + 48 + brow2) * 80 + (s * 2 + bch2) * 16);
            #pragma unroll
            for (int i = 0; i < 4; i++) {
                uint32_t aa = st + (wm * 64 + i * 16 + arow) * 80 + (s * 2 + ach) * 16;
                ldsm_x4(ah[i], aa);
            }
            #pragma unroll
            for (int i = 0; i < 4; i++)
                #pragma unroll
                for (int j = 0; j < 7; j++)
                    mma16816(acc[i*7+j], ah[i], bb[j]);
        }
        __syncthreads();
        if (kt + 3 < 32) issue(kt + 3, pbuf); else CP_COMMIT();
        buf  = (buf == 2)  ? 0 : buf + 1;
        pbuf = (pbuf == 2) ? 0 : pbuf + 1;
    }

    // ---- epilogue: fp16 bounce [n][ch] pitch 144, then uint4 biased stores
    __syncthreads();
    __half* eb = reinterpret_cast<__half*>(smc);
    #pragma unroll
    for (int i = 0; i < 4; i++)
        #pragma unroll
        for (int j = 0; j < 7; j++) {
            int ch  = wm * 64 + i * 16 + (lane >> 2);
            int col = wn * 56 + j * 8 + (lane & 3) * 2;
            eb[col * G1_EPITCH + ch]           = __float2half(acc[i*7+j][0]);
            eb[(col + 1) * G1_EPITCH + ch]     = __float2half(acc[i*7+j][1]);
            eb[col * G1_EPITCH + ch + 8]       = __float2half(acc[i*7+j][2]);
            eb[(col + 1) * G1_EPITCH + ch + 8] = __float2half(acc[i*7+j][3]);
        }
    __syncthreads();

    const bool isTheta = (m0 < CI);
    __half* dst = isTheta ? g_Th : g_Ph;
    const int ch0g = isTheta ? m0 : (m0 - CI);
    const float* bias = isTheta ? bth : bph;

    #pragma unroll
    for (int it = 0; it < 14; it++) {
        int t  = tid + it * 128;       // 0..1791
        int cg = t & 15, n = t >> 4;
        int chl = cg * 8;
        uint4 raw = *reinterpret_cast<const uint4*>(eb + n * G1_EPITCH + chl);
        const __half* rh = reinterpret_cast<const __half*>(&raw);
        __align__(16) __half h8[8];
        #pragma unroll
        for (int k = 0; k < 8; k++)
            h8[k] = __float2half(__half2float(rh[k]) + bias[ch0g + chl + k]);
        size_t off = ((size_t)b * NPOS + n0 + n) * CI + ch0g + chl;
        *reinterpret_cast<uint4*>(dst + off) = *reinterpret_cast<const uint4*>(h8);
    }
}

// ===========================================================================
// GEMM2 (warp MMA, fp16): F[n][m] = sum_k Th[n][k] Ph[m][k]
// CTA tile 128(n, clamped) x 112(m), 8 warps (4M x 2N), warp 32x56.
// K=64 stages, 2-stage pipeline (pitch 144B), 4 sub-iterations per barrier.
// Epilogue also emits per-colblock softmax partials (row max / sumexp).
// SMEM: max(2*34560=69120, 128*116*4=59392) = 69120
// ===========================================================================
#define G2_PITCH 144
#define G2_BOFF  18432           // A: 128 rows * 144B
#define G2_STAGE 34560           // + B: 112 rows * 144B
#define G2_SMEM  69120
#define G2_EPITCH 116

__global__ __launch_bounds__(256, 2) void gemm2_mma()
{
    extern __shared__ char smc[];
    const uint32_t sbase = smem_u32(smc);
    const int tid  = threadIdx.x;
    const int lane = tid & 31;
    const int wid  = tid >> 5;           // 0..7
    const int wm   = wid >> 1;           // 0..3  (rows n, 32 each)
    const int wn   = wid & 1;            // 0..1  (cols m, 56 each)
    const int b    = blockIdx.z;
    const int n0   = blockIdx.y * 128;   // rows (theta), padded range
    const int cbx  = blockIdx.x;         // col block 0..6
    const int mb0  = cbx * 112;          // cols (phi)

    float acc[14][4];
    #pragma unroll
    for (int i = 0; i < 14; i++)
        #pragma unroll
        for (int j = 0; j < 4; j++) acc[i][j] = 0.f;

    auto issue = [&](int kt, int buf) {
        const int k0 = kt * 64;
        const uint32_t st = sbase + buf * G2_STAGE;
        #pragma unroll
        for (int i = 0; i < 4; i++) {    // A: 1024 tasks, clamp row
            int t = tid + i * 256;
            int row = t >> 3, ch = t & 7;
            int gn = n0 + row; if (gn > NPOS - 1) gn = NPOS - 1;
            const __half* asrc = g_Th
                + ((size_t)b * NPOS + gn) * CI + k0 + ch * 8;
            cp16(st + row * G2_PITCH + ch * 16, asrc);
        }
        #pragma unroll
        for (int i = 0; i < 4; i++) {    // B: 896 tasks
            int t = tid + i * 256;
            if (t < 896) {
                int row = t >> 3, ch = t & 7;
                const __half* bsrc = g_Ph
                    + ((size_t)b * NPOS + mb0 + row) * CI + k0 + ch * 8;
                cp16(st + G2_BOFF + row * G2_PITCH + ch * 16, bsrc);
            }
        }
        CP_COMMIT();
    };

    issue(0, 0);
    issue(1, 1);

    const int arow = lane & 15;
    const int ach  = lane >> 4;
    const int brow = ((lane >> 4) << 3) + (lane & 7);
    const int bch  = (lane >> 3) & 1;
    const int brow2 = (lane & 15) & 7;
    const int bch2  = ((lane & 15) >> 3) & 1;

    int buf = 0;
    for (int kt = 0; kt < 8; kt++) {
        CP_WAIT_1();
        __syncthreads();
        const uint32_t st = sbase + buf * G2_STAGE;
        #pragma unroll
        for (int s = 0; s < 4; s++) {
            uint32_t ah[2][4], bb[7][2];
            #pragma unroll
            for (int i = 0; i < 2; i++) {
                uint32_t aa = st + (wm * 32 + i * 16 + arow) * G2_PITCH + (s * 2 + ach) * 16;
                ldsm_x4(ah[i], aa);
            }
            #pragma unroll
            for (int p = 0; p < 3; p++) {
                uint32_t ba = st + G2_BOFF + (wn * 56 + p * 16 + brow) * G2_PITCH + (s * 2 + bch) * 16;
                uint32_t r[4]; ldsm_x4(r, ba);
                bb[p*2][0] = r[0]; bb[p*2][1] = r[1];
                bb[p*2+1][0] = r[2]; bb[p*2+1][1] = r[3];
            }
            ldsm_x2(bb[6][0], bb[6][1],
                    st + G2_BOFF + (wn * 56 + 48 + brow2) * G2_PITCH + (s * 2 + bch2) * 16);
            #pragma unroll
            for (int i = 0; i < 2; i++)
                #pragma unroll
                for (int j = 0; j < 7; j++)
                    mma16816(acc[i*7+j], ah[i], bb[j]);
        }
        __syncthreads();
        if (kt + 2 < 8) issue(kt + 2, buf); else CP_COMMIT();
        buf ^= 1;
    }

    // epilogue: fp32 bounce [128][116], softmax partials + coalesced stores
    __syncthreads();
    float* eb = reinterpret_cast<float*>(smc);
    #pragma unroll
    for (int i = 0; i < 2; i++)
        #pragma unroll
        for (int j = 0; j < 7; j++) {
            int row = wm * 32 + i * 16 + (lane >> 2);
            int col = wn * 56 + j * 8 + (lane & 3) * 2;
            eb[row * G2_EPITCH + col]           = acc[i*7+j][0];
            eb[row * G2_EPITCH + col + 1]       = acc[i*7+j][1];
            eb[(row + 8) * G2_EPITCH + col]     = acc[i*7+j][2];
            eb[(row + 8) * G2_EPITCH + col + 1] = acc[i*7+j][3];
        }
    __syncthreads();

    // per-colblock row stats (tid<128, one row each)
    if (tid < 128 && n0 + tid < NPOS) {
        const float* row = eb + tid * G2_EPITCH;
        float mx = -CUDART_INF_F;
        #pragma unroll 4
        for (int j = 0; j < 112; j++) mx = fmaxf(mx, row[j]);
        float s = 0.f;
        #pragma unroll 4
        for (int j = 0; j < 112; j++) s += __expf(row[j] - mx);
        int o = (b * 7 + cbx) * NPOS + n0 + tid;
        g_pmax[o] = mx;
        g_psum[o] = s;
    }

    #pragma unroll
    for (int i = 0; i < 14; i++) {
        int t = tid + i * 256;          // 0..3583
        int row = t / 28, c4 = t % 28;
        if (n0 + row < NPOS) {
            float4 v = *reinterpret_cast<const float4*>(&eb[row * G2_EPITCH + c4 * 4]);
            *reinterpret_cast<float4*>(
                g_F + ((size_t)b * NPOS + n0 + row) * NPOS + mb0 + c4 * 4) = v;
        }
    }
}

// ===========================================================================
// combine per-colblock softmax partials -> rmax, rscale
// ===========================================================================
__global__ __launch_bounds__(256) void softmax_combine_kernel()
{
    int idx = blockIdx.x * 256 + threadIdx.x;     // over BATCH*NPOS
    if (idx >= BATCH * NPOS) return;
    int b = idx / NPOS, n = idx - b * NPOS;

    float mx = -CUDART_INF_F;
    float pm[7];
    #pragma unroll
    for (int cb = 0; cb < 7; cb++) {
        pm[cb] = g_pmax[(b * 7 + cb) * NPOS + n];
        mx = fmaxf(mx, pm[cb]);
    }
    float s = 0.f;
    #pragma unroll
    for (int cb = 0; cb < 7; cb++)
        s += g_psum[(b * 7 + cb) * NPOS + n] * __expf(pm[cb] - mx);

    g_rmax[idx]   = mx;
    g_rscale[idx] = 1.f / (s * (float)NPOS);
}

// a_bar[b][m] = sum_n exp(F[n][m]-rmax[n]) * rscale[n]
__global__ __launch_bounds__(112) void colsum_kernel()
{
    const int b  = blockIdx.z;
    const int m  = blockIdx.x * 112 + threadIdx.x;
    const int n0 = blockIdx.y * 112;

    __shared__ float srs[112];
    __shared__ float smx[112];
    srs[threadIdx.x] = g_rscale[b * NPOS + n0 + threadIdx.x];
    smx[threadIdx.x] = g_rmax[b * NPOS + n0 + threadIdx.x];
    __syncthreads();

    const float* __restrict__ Fb = g_F + ((size_t)b * NPOS + n0) * NPOS + m;
    float acc = 0.f;
    #pragma unroll 8
    for (int j = 0; j < 112; j++)
        acc += __expf(Fb[(size_t)j * NPOS] - smx[j]) * srs[j];
    atomicAdd(&g_abar[b * NPOS + m], acc);
}

__global__ __launch_bounds__(256) void xw_kernel(const float* __restrict__ x)
{
    const int b    = blockIdx.y;
    const int c    = blockIdx.x * 8 + (threadIdx.x >> 5);
    const int lane = threadIdx.x & 31;

    __shared__ float sa[NPOS];
    for (int i = threadIdx.x; i < NPOS; i += 256) sa[i] = g_abar[b * NPOS + i];
    __syncthreads();

    const float* __restrict__ xr = x + ((size_t)b * CDIM + c) * NPOS;
    float dot = 0.f, sum = 0.f;
    for (int i = lane; i < NPOS; i += 32) {
        float v = xr[i];
        dot = fmaf(v, sa[i], dot);
        sum += v;
    }
    #pragma unroll
    for (int o = 16; o; o >>= 1) {
        dot += __shfl_xor_sync(0xffffffffu, dot, o);
        sum += __shfl_xor_sync(0xffffffffu, sum, o);
    }
    if (lane == 0) {
        g_xw[b * CDIM + c]   = dot;
        g_xbar[b * CDIM + c] = sum * (1.f / (float)NPOS);
    }
}

__global__ __launch_bounds__(256) void ybar_kernel(const float* __restrict__ Wg,
                                                   const float* __restrict__ bg)
{
    const int b    = blockIdx.y;
    const int i    = blockIdx.x * 8 + (threadIdx.x >> 5);
    const int lane = threadIdx.x & 31;

    __shared__ float sx[CDIM];
    for (int k = threadIdx.x; k < CDIM; k += 256) sx[k] = g_xw[b * CDIM + k];
    __syncthreads();

    const float* __restrict__ w = Wg + (size_t)i * CDIM;
    float d = 0.f;
    for (int k = lane; k < CDIM; k += 32) d = fmaf(w[k], sx[k], d);
    #pragma unroll
    for (int o = 16; o; o >>= 1) d += __shfl_xor_sync(0xffffffffu, d, o);
    if (lane == 0) g_ybar[b * CI + i] = d + bg[i];
}

__global__ __launch_bounds__(256) void pooled_kernel(
    const float* __restrict__ Ww, const float* __restrict__ bw,
    const float* __restrict__ gamma, const float* __restrict__ beta,
    const float* __restrict__ bmean, const float* __restrict__ bvar)
{
    const int b    = blockIdx.y;
    const int c    = blockIdx.x * 8 + (threadIdx.x >> 5);
    const int lane = threadIdx.x & 31;

    __shared__ float sy[CI];
    for (int k = threadIdx.x; k < CI; k += 256) sy[k] = g_ybar[b * CI + k];
    __syncthreads();

    const float* __restrict__ w = Ww + (size_t)c * CI;
    float d = 0.f;
    for (int k = lane; k < CI; k += 32) d = fmaf(w[k], sy[k], d);
    #pragma unroll
    for (int o = 16; o; o >>= 1) d += __shfl_xor_sync(0xffffffffu, d, o);
    if (lane == 0) {
        float inv = gamma[c] * rsqrtf(bvar[c] + 1e-5f);
        g_pooled[b * CDIM + c] =
            inv * (d + bw[c]) + (beta[c] - bmean[c] * inv) + g_xbar[b * CDIM + c];
    }
}

__global__ __launch_bounds__(256) void h_kernel(const float* __restrict__ W1,
                                                const float* __restrict__ b1)
{
    const int b    = blockIdx.y;
    const int j    = blockIdx.x * 8 + (threadIdx.x >> 5);
    const int lane = threadIdx.x & 31;

    __shared__ float sp[CDIM];
    for (int k = threadIdx.x; k < CDIM; k += 256) sp[k] = g_pooled[b * CDIM + k];
    __syncthreads();

    const float* __restrict__ w = W1 + (size_t)j * CDIM;
    float d = 0.f;
    for (int k = lane; k < CDIM; k += 32) d = fmaf(w[k], sp[k], d);
    #pragma unroll
    for (int o = 16; o; o >>= 1) d += __shfl_xor_sync(0xffffffffu, d, o);
    if (lane == 0) g_h[b * CI + j] = d + b1[j];
}

__global__ __launch_bounds__(256) void out_kernel(const float* __restrict__ xface,
                                                  const float* __restrict__ W2,
                                                  const float* __restrict__ b2,
                                                  float* __restrict__ out)
{
    const int b = blockIdx.x;
    const int o = threadIdx.x >> 7;
    const int t = threadIdx.x & 127;

    float acc = 0.f;
    for (int k = t; k < CDIM; k += 128) {
        float v = (k < CI) ? g_h[b * CI + k] : xface[b * CI + (k - CI)];
        acc = fmaf(W2[o * CDIM + k], v, acc);
    }
    #pragma unroll
    for (int off = 16; off; off >>= 1) acc += __shfl_xor_sync(0xffffffffu, acc, off);

    __shared__ float sred[8];
    const int warp = threadIdx.x >> 5;
    if ((threadIdx.x & 31) == 0) sred[warp] = acc;
    __syncthreads();
    if (threadIdx.x == 0)
        out[b * 2 + 0] = sred[0] + sred[1] + sred[2] + sred[3] + b2[0];
    if (threadIdx.x == 128)
        out[b * 2 + 1] = sred[4] + sred[5] + sred[6] + sred[7] + b2[1];
}

// ===========================================================================
extern "C" void kernel_launch(void* const* d_in, const int* in_sizes, int n_in,
                              void* d_out, int out_size)
{
    const float* x_body = (const float*)d_in[0];
    const float* x_face = (const float*)d_in[1];
    const float* Wg     = (const float*)d_in[2];
    const float* bg     = (const float*)d_in[3];
    const float* Wth    = (const float*)d_in[4];
    const float* bth    = (const float*)d_in[5];
    const float* Wph    = (const float*)d_in[6];
    const float* bph    = (const float*)d_in[7];
    const float* Ww     = (const float*)d_in[8];
    const float* bw     = (const float*)d_in[9];
    const float* gamma  = (const float*)d_in[10];
    const float* beta   = (const float*)d_in[11];
    const float* bmean  = (const float*)d_in[12];
    const float* bvar   = (const float*)d_in[13];
    const float* W1     = (const float*)d_in[14];
    const float* b1     = (const float*)d_in[15];
    const float* W2     = (const float*)d_in[16];
    const float* b2     = (const float*)d_in[17];
    float* out = (float*)d_out;

    cudaFuncSetAttribute(gemm1_mma, cudaFuncAttributeMaxDynamicSharedMemorySize, G1_SMEM);
    cudaFuncSetAttribute(gemm2_mma, cudaFuncAttributeMaxDynamicSharedMemorySize, G2_SMEM);

    convert_W_kernel<<<(CDIM * CDIM) / 256, 256>>>(Wth, Wph);
    convert_X_kernel<<<dim3((NPOS + 31) / 32, CDIM / 32, BATCH), 256>>>(x_body);

    gemm1_mma<<<dim3(NPOS / 112, CDIM / 128, BATCH), 128, G1_SMEM>>>(bth, bph);
    gemm2_mma<<<dim3(NPOS / 112, (NPOS + 127) / 128, BATCH), 256, G2_SMEM>>>();

    softmax_combine_kernel<<<(BATCH * NPOS + 255) / 256, 256>>>();
    colsum_kernel<<<dim3(NPOS / 112, NPOS / 112, BATCH), 112>>>();
    xw_kernel<<<dim3(CDIM / 8, BATCH), 256>>>(x_body);
    ybar_kernel<<<dim3(CI / 8, BATCH), 256>>>(Wg, bg);
    pooled_kernel<<<dim3(CDIM / 8, BATCH), 256>>>(Ww, bw, gamma, beta, bmean, bvar);
    h_kernel<<<dim3(CI / 8, BATCH), 256>>>(W1, b1);
    out_kernel<<<BATCH, 256>>>(x_face, W2, b2, out);
}